// round 2
// baseline (speedup 1.0000x reference)
#include <cuda_runtime.h>
#include <mma.h>
using namespace nvcuda;

#define B_   2
#define T_   2048
#define DM   1024
#define H_   16
#define DH   64
#define ROWS (B_*T_)   // 4096

// Scratch (allocation-free rule -> __device__ globals). 4 x 16 MB.
__device__ float g_q[ROWS * DM];
__device__ float g_k[ROWS * DM];
__device__ float g_v[ROWS * DM];
__device__ float g_attn[ROWS * DM];

// ---------------------------------------------------------------------------
// Generic TF32 GEMM: C[M,N] = A[M,K] @ W[K,N], all row-major fp32.
// Block tile 64x64, K-tile 32, 4 warps (each warp: 16 rows x 64 cols, 4 frags).
// ---------------------------------------------------------------------------
template <int M, int N, int K>
__global__ void __launch_bounds__(128) gemm_tf32(const float* __restrict__ A,
                                                 const float* __restrict__ W,
                                                 float* __restrict__ C) {
    __shared__ float As[64 * 36];   // 64 rows x 32 k, ld 36 (pad)
    __shared__ float Bs[32 * 68];   // 32 k x 64 cols, ld 68 (pad)

    const int row0 = blockIdx.y * 64;
    const int col0 = blockIdx.x * 64;
    const int tid  = threadIdx.x;
    const int w    = tid >> 5;

    wmma::fragment<wmma::accumulator, 16, 16, 8, float> acc[4];
#pragma unroll
    for (int i = 0; i < 4; i++) wmma::fill_fragment(acc[i], 0.0f);

    for (int k0 = 0; k0 < K; k0 += 32) {
#pragma unroll
        for (int i = 0; i < 16; i++) {        // 64x32 = 2048 elems / 128 thr
            int e = i * 128 + tid;
            int r = e >> 5, c = e & 31;
            As[r * 36 + c] = wmma::__float_to_tf32(A[(row0 + r) * K + k0 + c]);
        }
#pragma unroll
        for (int i = 0; i < 16; i++) {        // 32x64 = 2048 elems / 128 thr
            int e = i * 128 + tid;
            int r = e >> 6, c = e & 63;
            Bs[r * 68 + c] = wmma::__float_to_tf32(W[(k0 + r) * N + col0 + c]);
        }
        __syncthreads();

#pragma unroll
        for (int kk = 0; kk < 4; kk++) {
            wmma::fragment<wmma::matrix_a, 16, 16, 8, wmma::precision::tf32, wmma::row_major> a;
            wmma::load_matrix_sync(a, As + (w * 16) * 36 + kk * 8, 36);
#pragma unroll
            for (int nf = 0; nf < 4; nf++) {
                wmma::fragment<wmma::matrix_b, 16, 16, 8, wmma::precision::tf32, wmma::row_major> b;
                wmma::load_matrix_sync(b, Bs + (kk * 8) * 68 + nf * 16, 68);
                wmma::mma_sync(acc[nf], a, b, acc[nf]);
            }
        }
        __syncthreads();
    }

#pragma unroll
    for (int nf = 0; nf < 4; nf++)
        wmma::store_matrix_sync(C + (row0 + w * 16) * N + col0 + nf * 16,
                                acc[nf], N, wmma::mem_row_major);
}

// ---------------------------------------------------------------------------
// Fused masked attention (no softmax): per (b,h), query tile of 64 rows,
// stream key/value tiles of 32. O[t,:] = sum_{s<t} (q_t . k_s) * v_s
// 4 warps; warp w owns query rows [w*16, w*16+16) and the full 64 d-cols.
// ---------------------------------------------------------------------------
__global__ void __launch_bounds__(128) attn_kernel() {
    __shared__ float Qs[64 * 68];   // 17408 B
    __shared__ float Ks[32 * 68];   //  8704 B
    __shared__ float Vs[32 * 68];   //  8704 B
    __shared__ float Ss[64 * 36];   //  9216 B   (total 44032 B)

    const int t0   = blockIdx.x * 64;
    const int bh   = blockIdx.y;
    const int b    = bh >> 4;       // H_ = 16
    const int h    = bh & 15;
    const int tid  = threadIdx.x;
    const int w    = tid >> 5;
    const int lane = tid & 31;

    const float* Qg = g_q + (size_t)(b * T_ + t0) * DM + h * DH;

#pragma unroll
    for (int i = 0; i < 32; i++) {            // 64x64 Q tile
        int e = i * 128 + tid;
        int r = e >> 6, c = e & 63;
        Qs[r * 68 + c] = wmma::__float_to_tf32(Qg[r * DM + c]);
    }

    wmma::fragment<wmma::accumulator, 16, 16, 8, float> o[4];
#pragma unroll
    for (int i = 0; i < 4; i++) wmma::fill_fragment(o[i], 0.0f);
    __syncthreads();

    const int sEnd = t0 + 32;   // last key tile start needed for strict-lower mask
    for (int s0 = 0; s0 <= sEnd; s0 += 32) {
        const float* Kg = g_k + (size_t)(b * T_ + s0) * DM + h * DH;
        const float* Vg = g_v + (size_t)(b * T_ + s0) * DM + h * DH;
#pragma unroll
        for (int i = 0; i < 16; i++) {        // 32x64 K and V tiles
            int e = i * 128 + tid;
            int r = e >> 6, c = e & 63;
            Ks[r * 68 + c] = wmma::__float_to_tf32(Kg[r * DM + c]);
            Vs[r * 68 + c] = wmma::__float_to_tf32(Vg[r * DM + c]);
        }
        __syncthreads();

        // S[16x32] = Q_stripe[16x64] @ K_tile^T  (K row-major -> matrix_b col_major)
        wmma::fragment<wmma::accumulator, 16, 16, 8, float> s_acc[2];
        wmma::fill_fragment(s_acc[0], 0.0f);
        wmma::fill_fragment(s_acc[1], 0.0f);
#pragma unroll
        for (int kk = 0; kk < 8; kk++) {
            wmma::fragment<wmma::matrix_a, 16, 16, 8, wmma::precision::tf32, wmma::row_major> a;
            wmma::load_matrix_sync(a, Qs + (w * 16) * 68 + kk * 8, 68);
#pragma unroll
            for (int nf = 0; nf < 2; nf++) {
                wmma::fragment<wmma::matrix_b, 16, 16, 8, wmma::precision::tf32, wmma::col_major> bf;
                wmma::load_matrix_sync(bf, Ks + (nf * 16) * 68 + kk * 8, 68);
                wmma::mma_sync(s_acc[nf], a, bf, s_acc[nf]);
            }
        }
        wmma::store_matrix_sync(Ss + (w * 16) * 36,      s_acc[0], 36, wmma::mem_row_major);
        wmma::store_matrix_sync(Ss + (w * 16) * 36 + 16, s_acc[1], 36, wmma::mem_row_major);
        __syncwarp();

        // Strictly-lower mask (keep s < t) on the diagonal-adjacent tiles + tf32 convert
        const bool need_mask = (s0 + 31 >= t0);
#pragma unroll
        for (int i = 0; i < 16; i++) {        // 16x32 stripe / 32 lanes
            int e = i * 32 + lane;
            int r = e >> 5, c = e & 31;
            float v = Ss[(w * 16 + r) * 36 + c];
            if (need_mask && (s0 + c >= t0 + w * 16 + r)) v = 0.0f;
            Ss[(w * 16 + r) * 36 + c] = wmma::__float_to_tf32(v);
        }
        __syncwarp();

        // O_stripe[16x64] += S[16x32] @ V_tile[32x64]
#pragma unroll
        for (int kk = 0; kk < 4; kk++) {
            wmma::fragment<wmma::matrix_a, 16, 16, 8, wmma::precision::tf32, wmma::row_major> a;
            wmma::load_matrix_sync(a, Ss + (w * 16) * 36 + kk * 8, 36);
#pragma unroll
            for (int nf = 0; nf < 4; nf++) {
                wmma::fragment<wmma::matrix_b, 16, 16, 8, wmma::precision::tf32, wmma::row_major> bf;
                wmma::load_matrix_sync(bf, Vs + (kk * 8) * 68 + nf * 16, 68);
                wmma::mma_sync(o[nf], a, bf, o[nf]);
            }
        }
        __syncthreads();
    }

    float* Og = g_attn + (size_t)(b * T_ + t0 + w * 16) * DM + h * DH;
#pragma unroll
    for (int nf = 0; nf < 4; nf++)
        wmma::store_matrix_sync(Og + nf * 16, o[nf], DM, wmma::mem_row_major);
}

// ---------------------------------------------------------------------------
extern "C" void kernel_launch(void* const* d_in, const int* in_sizes, int n_in,
                              void* d_out, int out_size) {
    const float* x  = (const float*)d_in[0];
    const float* Wq = (const float*)d_in[1];
    const float* Wk = (const float*)d_in[2];
    const float* Wv = (const float*)d_in[3];
    const float* Wo = (const float*)d_in[4];

    float *q, *k, *v, *attn;
    cudaGetSymbolAddress((void**)&q,    g_q);
    cudaGetSymbolAddress((void**)&k,    g_k);
    cudaGetSymbolAddress((void**)&v,    g_v);
    cudaGetSymbolAddress((void**)&attn, g_attn);

    dim3 gb(128);
    dim3 gg(DM / 64, ROWS / 64);          // (16, 64)

    gemm_tf32<ROWS, DM, DM><<<gg, gb>>>(x, Wq, q);
    gemm_tf32<ROWS, DM, DM><<<gg, gb>>>(x, Wk, k);
    gemm_tf32<ROWS, DM, DM><<<gg, gb>>>(x, Wv, v);

    attn_kernel<<<dim3(T_ / 64, B_ * H_), 128>>>();   // (32, 32)

    gemm_tf32<ROWS, DM, DM><<<gg, gb>>>(attn, Wo, (float*)d_out);
}

// round 3
// speedup vs baseline: 1.6108x; 1.6108x over previous
#include <cuda_runtime.h>
#include <mma.h>
#include <cstdint>
using namespace nvcuda;

#define B_   2
#define T_   2048
#define DM   1024
#define H_   16
#define DH   64
#define ROWS (B_*T_)       // 4096
#define CH   64            // attention chunk size
#define NCH  (T_/CH)       // 32
#define BH   (B_*H_)       // 32

// Scratch (allocation-free rule -> __device__ globals)
__device__ float g_q[ROWS*DM];
__device__ float g_k[ROWS*DM];
__device__ float g_v[ROWS*DM];
__device__ float g_attn[ROWS*DM];
__device__ float g_kv[(size_t)BH*NCH*DH*DH];   // per-chunk K^T V
__device__ float g_m [(size_t)BH*NCH*DH*DH];   // exclusive prefix of g_kv

__device__ __forceinline__ void cp16(float* dst, const float* src) {
    uint32_t d = (uint32_t)__cvta_generic_to_shared(dst);
    asm volatile("cp.async.cg.shared.global [%0], [%1], 16;\n" :: "r"(d), "l"(src));
}

// ---------------------------------------------------------------------------
// TF32 GEMM: C[M,N] = A[M,K] @ W[K,N]. Block tile 128x64, ktile 32,
// 8 warps (4x2 grid of 32x32 warp tiles), cp.async double buffering.
// ---------------------------------------------------------------------------
template <int MM, int NN, int KK>
__global__ void __launch_bounds__(256) gemm_tf32(const float* __restrict__ A,
                                                 const float* __restrict__ W,
                                                 float* __restrict__ C) {
    extern __shared__ float sm[];
    float* As = sm;                    // 2 x [128][36]
    float* Bs = sm + 2 * 128 * 36;     // 2 x [32][68]

    const int row0 = blockIdx.y * 128;
    const int col0 = blockIdx.x * 64;
    const int tid  = threadIdx.x;
    const int w    = tid >> 5;
    const int wr   = w & 3;            // warp row group (32 rows)
    const int wc   = w >> 2;           // warp col group (32 cols)

    wmma::fragment<wmma::accumulator, 16, 16, 8, float> acc[2][2];
#pragma unroll
    for (int i = 0; i < 2; i++)
#pragma unroll
        for (int j = 0; j < 2; j++) wmma::fill_fragment(acc[i][j], 0.0f);

    auto issue = [&](int kt, int buf) {
        const int k0 = kt * 32;
        float* Ad = As + buf * (128 * 36);
        float* Bd = Bs + buf * (32 * 68);
#pragma unroll
        for (int i = 0; i < 4; i++) {          // A: 128x32 = 1024 float4
            int id = tid + i * 256;
            int r = id >> 3, c = (id & 7) * 4;
            cp16(Ad + r * 36 + c, A + (size_t)(row0 + r) * KK + k0 + c);
        }
#pragma unroll
        for (int i = 0; i < 2; i++) {          // B: 32x64 = 512 float4
            int id = tid + i * 256;
            int r = id >> 4, c = (id & 15) * 4;
            cp16(Bd + r * 68 + c, W + (size_t)(k0 + r) * NN + col0 + c);
        }
        asm volatile("cp.async.commit_group;\n");
    };

    issue(0, 0);
    const int NT = KK / 32;
    for (int kt = 0; kt < NT; kt++) {
        const int cur = kt & 1;
        if (kt + 1 < NT) {
            issue(kt + 1, cur ^ 1);
            asm volatile("cp.async.wait_group 1;\n");
        } else {
            asm volatile("cp.async.wait_group 0;\n");
        }
        __syncthreads();

        const float* Ac = As + cur * (128 * 36);
        const float* Bc = Bs + cur * (32 * 68);
#pragma unroll
        for (int kk = 0; kk < 4; kk++) {
            wmma::fragment<wmma::matrix_a, 16, 16, 8, wmma::precision::tf32, wmma::row_major> a[2];
#pragma unroll
            for (int i = 0; i < 2; i++) {
                wmma::load_matrix_sync(a[i], Ac + (wr * 32 + i * 16) * 36 + kk * 8, 36);
#pragma unroll
                for (int e = 0; e < a[i].num_elements; e++)
                    a[i].x[e] = wmma::__float_to_tf32(a[i].x[e]);
            }
            wmma::fragment<wmma::matrix_b, 16, 16, 8, wmma::precision::tf32, wmma::row_major> b[2];
#pragma unroll
            for (int j = 0; j < 2; j++) {
                wmma::load_matrix_sync(b[j], Bc + (kk * 8) * 68 + wc * 32 + j * 16, 68);
#pragma unroll
                for (int e = 0; e < b[j].num_elements; e++)
                    b[j].x[e] = wmma::__float_to_tf32(b[j].x[e]);
            }
#pragma unroll
            for (int i = 0; i < 2; i++)
#pragma unroll
                for (int j = 0; j < 2; j++)
                    wmma::mma_sync(acc[i][j], a[i], b[j], acc[i][j]);
        }
        __syncthreads();
    }

#pragma unroll
    for (int i = 0; i < 2; i++)
#pragma unroll
        for (int j = 0; j < 2; j++)
            wmma::store_matrix_sync(C + (size_t)(row0 + wr * 32 + i * 16) * NN
                                      + col0 + wc * 32 + j * 16,
                                    acc[i][j], NN, wmma::mem_row_major);
}

// ---------------------------------------------------------------------------
// Phase 1: per-chunk KV_c = K_c^T @ V_c  (64x64, k-dim 64), 3xTF32.
// ---------------------------------------------------------------------------
__global__ void __launch_bounds__(128) chunk_kv() {
    __shared__ float Ks[CH * 68];
    __shared__ float Vs[CH * 68];
    const int ch = blockIdx.x, bh = blockIdx.y;
    const int b = bh >> 4, h = bh & 15;
    const int tid = threadIdx.x, w = tid >> 5;

    const float* Kg = g_k + (size_t)(b * T_ + ch * CH) * DM + h * DH;
    const float* Vg = g_v + (size_t)(b * T_ + ch * CH) * DM + h * DH;
#pragma unroll
    for (int i = 0; i < 8; i++) {          // 64x64 = 1024 float4 each
        int id = tid + i * 128;
        int r = id >> 4, c = (id & 15) * 4;
        *(float4*)(Ks + r * 68 + c) = *(const float4*)(Kg + (size_t)r * DM + c);
        *(float4*)(Vs + r * 68 + c) = *(const float4*)(Vg + (size_t)r * DM + c);
    }
    __syncthreads();

    wmma::fragment<wmma::accumulator, 16, 16, 8, float> acc[4];
#pragma unroll
    for (int i = 0; i < 4; i++) wmma::fill_fragment(acc[i], 0.0f);

#pragma unroll
    for (int kk = 0; kk < 8; kk++) {       // s dimension (64) in chunks of 8
        // A = K^T : col_major over Ks. rows=d (16w..), cols=s (8kk..)
        wmma::fragment<wmma::matrix_a, 16, 16, 8, wmma::precision::tf32, wmma::col_major> ah, al;
        wmma::load_matrix_sync(ah, Ks + (kk * 8) * 68 + w * 16, 68);
#pragma unroll
        for (int e = 0; e < ah.num_elements; e++) {
            float x = ah.x[e];
            float hi = wmma::__float_to_tf32(x);
            ah.x[e] = hi;
            al.x[e] = wmma::__float_to_tf32(x - hi);
        }
#pragma unroll
        for (int nf = 0; nf < 4; nf++) {
            wmma::fragment<wmma::matrix_b, 16, 16, 8, wmma::precision::tf32, wmma::row_major> bhi, blo;
            wmma::load_matrix_sync(bhi, Vs + (kk * 8) * 68 + nf * 16, 68);
#pragma unroll
            for (int e = 0; e < bhi.num_elements; e++) {
                float x = bhi.x[e];
                float hi = wmma::__float_to_tf32(x);
                bhi.x[e] = hi;
                blo.x[e] = wmma::__float_to_tf32(x - hi);
            }
            wmma::mma_sync(acc[nf], ah, bhi, acc[nf]);
            wmma::mma_sync(acc[nf], ah, blo, acc[nf]);
            wmma::mma_sync(acc[nf], al, bhi, acc[nf]);
        }
    }

    float* out = g_kv + ((size_t)bh * NCH + ch) * DH * DH;
#pragma unroll
    for (int nf = 0; nf < 4; nf++)
        wmma::store_matrix_sync(out + (w * 16) * DH + nf * 16, acc[nf], DH,
                                wmma::mem_row_major);
}

// ---------------------------------------------------------------------------
// Phase 2: exclusive prefix over chunks: M_c = sum_{c'<c} KV_{c'}  (fp32 exact)
// grid (8, BH), 512 threads: each thread owns one of the 4096 matrix elements.
// ---------------------------------------------------------------------------
__global__ void __launch_bounds__(512) prefix_kv() {
    const int bh = blockIdx.y;
    const int e  = blockIdx.x * 512 + threadIdx.x;
    const size_t base = (size_t)bh * NCH * DH * DH;
    float run = 0.0f;
#pragma unroll
    for (int c = 0; c < NCH; c++) {
        g_m[base + (size_t)c * (DH * DH) + e] = run;
        run += g_kv[base + (size_t)c * (DH * DH) + e];
    }
}

// ---------------------------------------------------------------------------
// Phase 3: O_c = Q_c @ M_c (3xTF32) + mask(Q_c K_c^T) @ V_c (tf32)
// Block = one (b,h,chunk). 4 warps; warp w owns rows 16w..16w+15.
// ---------------------------------------------------------------------------
__global__ void __launch_bounds__(128) attn_chunk() {
    extern __shared__ float sm3[];
    float* Qs = sm3;               // 64x68 raw fp32
    float* Ks = Qs + 64 * 68;
    float* Vs = Ks + 64 * 68;
    float* Ms = Vs + 64 * 68;
    float* Ss = Ms + 64 * 68;

    const int ch = blockIdx.x, bh = blockIdx.y;
    const int b = bh >> 4, h = bh & 15;
    const int t0 = ch * CH;
    const int tid = threadIdx.x, w = tid >> 5, lane = tid & 31;

    const float* Qg = g_q + (size_t)(b * T_ + t0) * DM + h * DH;
    const float* Kg = g_k + (size_t)(b * T_ + t0) * DM + h * DH;
    const float* Vg = g_v + (size_t)(b * T_ + t0) * DM + h * DH;
    const float* Mg = g_m + ((size_t)bh * NCH + ch) * DH * DH;

#pragma unroll
    for (int i = 0; i < 8; i++) {
        int id = tid + i * 128;
        int r = id >> 4, c = (id & 15) * 4;
        *(float4*)(Qs + r * 68 + c) = *(const float4*)(Qg + (size_t)r * DM + c);
        *(float4*)(Ks + r * 68 + c) = *(const float4*)(Kg + (size_t)r * DM + c);
        *(float4*)(Vs + r * 68 + c) = *(const float4*)(Vg + (size_t)r * DM + c);
        *(float4*)(Ms + r * 68 + c) = *(const float4*)(Mg + id * 4);
    }
    __syncthreads();

    wmma::fragment<wmma::accumulator, 16, 16, 8, float> o[4];
#pragma unroll
    for (int i = 0; i < 4; i++) wmma::fill_fragment(o[i], 0.0f);

    // (a) O = Q @ M  with 3xTF32 (hi*hi + hi*lo + lo*hi)
#pragma unroll
    for (int kk = 0; kk < 8; kk++) {
        wmma::fragment<wmma::matrix_a, 16, 16, 8, wmma::precision::tf32, wmma::row_major> ah, al;
        wmma::load_matrix_sync(ah, Qs + (w * 16) * 68 + kk * 8, 68);
#pragma unroll
        for (int e = 0; e < ah.num_elements; e++) {
            float x = ah.x[e];
            float hi = wmma::__float_to_tf32(x);
            ah.x[e] = hi;
            al.x[e] = wmma::__float_to_tf32(x - hi);
        }
#pragma unroll
        for (int nf = 0; nf < 4; nf++) {
            wmma::fragment<wmma::matrix_b, 16, 16, 8, wmma::precision::tf32, wmma::row_major> bhi, blo;
            wmma::load_matrix_sync(bhi, Ms + (kk * 8) * 68 + nf * 16, 68);
#pragma unroll
            for (int e = 0; e < bhi.num_elements; e++) {
                float x = bhi.x[e];
                float hi = wmma::__float_to_tf32(x);
                bhi.x[e] = hi;
                blo.x[e] = wmma::__float_to_tf32(x - hi);
            }
            wmma::mma_sync(o[nf], ah, bhi, o[nf]);
            wmma::mma_sync(o[nf], ah, blo, o[nf]);
            wmma::mma_sync(o[nf], al, bhi, o[nf]);
        }
    }

    // (b) S = Q @ K^T  (intra-chunk scores)
    wmma::fragment<wmma::accumulator, 16, 16, 8, float> s_acc[4];
#pragma unroll
    for (int i = 0; i < 4; i++) wmma::fill_fragment(s_acc[i], 0.0f);
#pragma unroll
    for (int kk = 0; kk < 8; kk++) {
        wmma::fragment<wmma::matrix_a, 16, 16, 8, wmma::precision::tf32, wmma::row_major> a;
        wmma::load_matrix_sync(a, Qs + (w * 16) * 68 + kk * 8, 68);
#pragma unroll
        for (int e = 0; e < a.num_elements; e++) a.x[e] = wmma::__float_to_tf32(a.x[e]);
#pragma unroll
        for (int nf = 0; nf < 4; nf++) {
            wmma::fragment<wmma::matrix_b, 16, 16, 8, wmma::precision::tf32, wmma::col_major> bb;
            wmma::load_matrix_sync(bb, Ks + (nf * 16) * 68 + kk * 8, 68);
#pragma unroll
            for (int e = 0; e < bb.num_elements; e++) bb.x[e] = wmma::__float_to_tf32(bb.x[e]);
            wmma::mma_sync(s_acc[nf], a, bb, s_acc[nf]);
        }
    }
#pragma unroll
    for (int nf = 0; nf < 4; nf++)
        wmma::store_matrix_sync(Ss + (w * 16) * 68 + nf * 16, s_acc[nf], 68,
                                wmma::mem_row_major);
    __syncwarp();

    // strictly-lower mask within chunk: keep col < row
#pragma unroll
    for (int i = 0; i < 32; i++) {             // 16x64 stripe / 32 lanes
        int e = i * 32 + lane;
        int r = e >> 6, c = e & 63;
        if (c >= w * 16 + r) Ss[(w * 16 + r) * 68 + c] = 0.0f;
    }
    __syncwarp();

    // (c) O += S @ V
#pragma unroll
    for (int kk = 0; kk < 8; kk++) {
        wmma::fragment<wmma::matrix_a, 16, 16, 8, wmma::precision::tf32, wmma::row_major> a;
        wmma::load_matrix_sync(a, Ss + (w * 16) * 68 + kk * 8, 68);
#pragma unroll
        for (int e = 0; e < a.num_elements; e++) a.x[e] = wmma::__float_to_tf32(a.x[e]);
#pragma unroll
        for (int nf = 0; nf < 4; nf++) {
            wmma::fragment<wmma::matrix_b, 16, 16, 8, wmma::precision::tf32, wmma::row_major> bb;
            wmma::load_matrix_sync(bb, Vs + (kk * 8) * 68 + nf * 16, 68);
#pragma unroll
            for (int e = 0; e < bb.num_elements; e++) bb.x[e] = wmma::__float_to_tf32(bb.x[e]);
            wmma::mma_sync(o[nf], a, bb, o[nf]);
        }
    }

    float* Og = g_attn + (size_t)(b * T_ + t0 + w * 16) * DM + h * DH;
#pragma unroll
    for (int nf = 0; nf < 4; nf++)
        wmma::store_matrix_sync(Og + nf * 16, o[nf], DM, wmma::mem_row_major);
}

// ---------------------------------------------------------------------------
extern "C" void kernel_launch(void* const* d_in, const int* in_sizes, int n_in,
                              void* d_out, int out_size) {
    const float* x  = (const float*)d_in[0];
    const float* Wq = (const float*)d_in[1];
    const float* Wk = (const float*)d_in[2];
    const float* Wv = (const float*)d_in[3];
    const float* Wo = (const float*)d_in[4];

    float *q, *k, *v, *attn;
    cudaGetSymbolAddress((void**)&q,    g_q);
    cudaGetSymbolAddress((void**)&k,    g_k);
    cudaGetSymbolAddress((void**)&v,    g_v);
    cudaGetSymbolAddress((void**)&attn, g_attn);

    constexpr int GEMM_SMEM = (2 * 128 * 36 + 2 * 32 * 68) * 4;   // 54272
    constexpr int ATTN_SMEM = 5 * 64 * 68 * 4;                    // 87040
    cudaFuncSetAttribute(gemm_tf32<ROWS, DM, DM>,
                         cudaFuncAttributeMaxDynamicSharedMemorySize, GEMM_SMEM);
    cudaFuncSetAttribute(attn_chunk,
                         cudaFuncAttributeMaxDynamicSharedMemorySize, ATTN_SMEM);

    dim3 gg(DM / 64, ROWS / 128);    // (16, 32)

    gemm_tf32<ROWS, DM, DM><<<gg, 256, GEMM_SMEM>>>(x, Wq, q);
    gemm_tf32<ROWS, DM, DM><<<gg, 256, GEMM_SMEM>>>(x, Wk, k);
    gemm_tf32<ROWS, DM, DM><<<gg, 256, GEMM_SMEM>>>(x, Wv, v);

    chunk_kv<<<dim3(NCH, BH), 128>>>();
    prefix_kv<<<dim3(8, BH), 512>>>();
    attn_chunk<<<dim3(NCH, BH), 128, ATTN_SMEM>>>();

    gemm_tf32<ROWS, DM, DM><<<gg, 256, GEMM_SMEM>>>(attn, Wo, (float*)d_out);
}

// round 5
// speedup vs baseline: 1.6521x; 1.0256x over previous
#include <cuda_runtime.h>
#include <mma.h>
#include <cstdint>
using namespace nvcuda;

#define B_   2
#define T_   2048
#define DM   1024
#define H_   16
#define DH   64
#define ROWS (B_*T_)       // 4096
#define CH   64
#define NCH  (T_/CH)       // 32
#define BH   (B_*H_)       // 32

// Scratch (allocation-free rule -> __device__ globals)
__device__ float g_q[ROWS*DM];
__device__ float g_k[ROWS*DM];
__device__ float g_v[ROWS*DM];
__device__ float g_attn[ROWS*DM];
__device__ float g_xr[ROWS*DM];          // x rounded to tf32
__device__ float g_wr[4*DM*DM];          // Wq|Wk|Wv|Wo rounded to tf32
__device__ float g_kv[(size_t)BH*NCH*DH*DH];
__device__ float g_m [(size_t)BH*NCH*DH*DH];

__device__ __forceinline__ void cp16(float* dst, const float* src) {
    uint32_t d = (uint32_t)__cvta_generic_to_shared(dst);
    asm volatile("cp.async.cg.shared.global [%0], [%1], 16;\n" :: "r"(d), "l"(src));
}

// ---------------------------------------------------------------------------
// Pre-pass: round a buffer to exact tf32 values (so GEMM needs no conversion).
// ---------------------------------------------------------------------------
__global__ void __launch_bounds__(256) round_buf(const float4* __restrict__ src,
                                                 float4* __restrict__ dst) {
    int i = blockIdx.x * 256 + threadIdx.x;
    float4 v = src[i];
    v.x = wmma::__float_to_tf32(v.x);
    v.y = wmma::__float_to_tf32(v.y);
    v.z = wmma::__float_to_tf32(v.z);
    v.w = wmma::__float_to_tf32(v.w);
    dst[i] = v;
}

// ---------------------------------------------------------------------------
// TF32 GEMM on pre-rounded inputs: C[M,N] = A[M,K] @ W[K,N].
// Block tile 128x128, ktile 32, 8 warps (4x2 grid of 32x64 warp tiles),
// cp.async double buffering. NO conversions in the hot loop.
// ---------------------------------------------------------------------------
#define GN 1024
#define GK 1024
#define LDA 36
#define LDB 132

__global__ void __launch_bounds__(256) gemm_tf32(const float* __restrict__ A,
                                                 const float* __restrict__ W,
                                                 float* __restrict__ C) {
    extern __shared__ float sm[];
    float* As = sm;                        // 2 x [128][36]
    float* Bs = sm + 2 * 128 * LDA;        // 2 x [32][132]

    const int row0 = blockIdx.y * 128;
    const int col0 = blockIdx.x * 128;
    const int tid  = threadIdx.x;
    const int w    = tid >> 5;
    const int wr   = w & 3;                // 4 row groups of 32
    const int wc   = w >> 2;               // 2 col groups of 64

    wmma::fragment<wmma::accumulator, 16, 16, 8, float> acc[2][4];
#pragma unroll
    for (int i = 0; i < 2; i++)
#pragma unroll
        for (int j = 0; j < 4; j++) wmma::fill_fragment(acc[i][j], 0.0f);

    auto issue = [&](int kt, int buf) {
        const int k0 = kt * 32;
        float* Ad = As + buf * (128 * LDA);
        float* Bd = Bs + buf * (32 * LDB);
#pragma unroll
        for (int i = 0; i < 4; i++) {          // A: 128x32 = 1024 float4
            int id = tid + i * 256;
            int r = id >> 3, c = (id & 7) * 4;
            cp16(Ad + r * LDA + c, A + (size_t)(row0 + r) * GK + k0 + c);
        }
#pragma unroll
        for (int i = 0; i < 4; i++) {          // B: 32x128 = 1024 float4
            int id = tid + i * 256;
            int r = id >> 5, c = (id & 31) * 4;
            cp16(Bd + r * LDB + c, W + (size_t)(k0 + r) * GN + col0 + c);
        }
        asm volatile("cp.async.commit_group;\n");
    };

    issue(0, 0);
    const int NT = GK / 32;
    for (int kt = 0; kt < NT; kt++) {
        const int cur = kt & 1;
        if (kt + 1 < NT) {
            issue(kt + 1, cur ^ 1);
            asm volatile("cp.async.wait_group 1;\n");
        } else {
            asm volatile("cp.async.wait_group 0;\n");
        }
        __syncthreads();

        const float* Ac = As + cur * (128 * LDA);
        const float* Bc = Bs + cur * (32 * LDB);
#pragma unroll
        for (int kk = 0; kk < 4; kk++) {
            wmma::fragment<wmma::matrix_a, 16, 16, 8, wmma::precision::tf32, wmma::row_major> a[2];
#pragma unroll
            for (int i = 0; i < 2; i++)
                wmma::load_matrix_sync(a[i], Ac + (wr * 32 + i * 16) * LDA + kk * 8, LDA);
            wmma::fragment<wmma::matrix_b, 16, 16, 8, wmma::precision::tf32, wmma::row_major> b[4];
#pragma unroll
            for (int j = 0; j < 4; j++)
                wmma::load_matrix_sync(b[j], Bc + (kk * 8) * LDB + wc * 64 + j * 16, LDB);
#pragma unroll
            for (int i = 0; i < 2; i++)
#pragma unroll
                for (int j = 0; j < 4; j++)
                    wmma::mma_sync(acc[i][j], a[i], b[j], acc[i][j]);
        }
        __syncthreads();
    }

#pragma unroll
    for (int i = 0; i < 2; i++)
#pragma unroll
        for (int j = 0; j < 4; j++)
            wmma::store_matrix_sync(C + (size_t)(row0 + wr * 32 + i * 16) * GN
                                      + col0 + wc * 64 + j * 16,
                                    acc[i][j], GN, wmma::mem_row_major);
}

// ---------------------------------------------------------------------------
// Phase 1: per-chunk KV_c = K_c^T @ V_c  (64x64, k-dim 64), 3xTF32.
// ---------------------------------------------------------------------------
__global__ void __launch_bounds__(128) chunk_kv() {
    __shared__ float Ks[CH * 68];
    __shared__ float Vs[CH * 68];
    const int ch = blockIdx.x, bh = blockIdx.y;
    const int b = bh >> 4, h = bh & 15;
    const int tid = threadIdx.x, w = tid >> 5;

    const float* Kg = g_k + (size_t)(b * T_ + ch * CH) * DM + h * DH;
    const float* Vg = g_v + (size_t)(b * T_ + ch * CH) * DM + h * DH;
#pragma unroll
    for (int i = 0; i < 8; i++) {
        int id = tid + i * 128;
        int r = id >> 4, c = (id & 15) * 4;
        *(float4*)(Ks + r * 68 + c) = *(const float4*)(Kg + (size_t)r * DM + c);
        *(float4*)(Vs + r * 68 + c) = *(const float4*)(Vg + (size_t)r * DM + c);
    }
    __syncthreads();

    wmma::fragment<wmma::accumulator, 16, 16, 8, float> acc[4];
#pragma unroll
    for (int i = 0; i < 4; i++) wmma::fill_fragment(acc[i], 0.0f);

#pragma unroll
    for (int kk = 0; kk < 8; kk++) {
        wmma::fragment<wmma::matrix_a, 16, 16, 8, wmma::precision::tf32, wmma::col_major> ah, al;
        wmma::load_matrix_sync(ah, Ks + (kk * 8) * 68 + w * 16, 68);
#pragma unroll
        for (int e = 0; e < ah.num_elements; e++) {
            float x = ah.x[e];
            float hi = wmma::__float_to_tf32(x);
            ah.x[e] = hi;
            al.x[e] = wmma::__float_to_tf32(x - hi);
        }
#pragma unroll
        for (int nf = 0; nf < 4; nf++) {
            wmma::fragment<wmma::matrix_b, 16, 16, 8, wmma::precision::tf32, wmma::row_major> bhi, blo;
            wmma::load_matrix_sync(bhi, Vs + (kk * 8) * 68 + nf * 16, 68);
#pragma unroll
            for (int e = 0; e < bhi.num_elements; e++) {
                float x = bhi.x[e];
                float hi = wmma::__float_to_tf32(x);
                bhi.x[e] = hi;
                blo.x[e] = wmma::__float_to_tf32(x - hi);
            }
            wmma::mma_sync(acc[nf], ah, bhi, acc[nf]);
            wmma::mma_sync(acc[nf], ah, blo, acc[nf]);
            wmma::mma_sync(acc[nf], al, bhi, acc[nf]);
        }
    }

    float* out = g_kv + ((size_t)bh * NCH + ch) * DH * DH;
#pragma unroll
    for (int nf = 0; nf < 4; nf++)
        wmma::store_matrix_sync(out + (w * 16) * DH + nf * 16, acc[nf], DH,
                                wmma::mem_row_major);
}

// ---------------------------------------------------------------------------
// Phase 2: exclusive prefix over chunks (fp32 exact).
// ---------------------------------------------------------------------------
__global__ void __launch_bounds__(512) prefix_kv() {
    const int bh = blockIdx.y;
    const int e  = blockIdx.x * 512 + threadIdx.x;
    const size_t base = (size_t)bh * NCH * DH * DH;
    float run = 0.0f;
#pragma unroll
    for (int c = 0; c < NCH; c++) {
        g_m[base + (size_t)c * (DH * DH) + e] = run;
        run += g_kv[base + (size_t)c * (DH * DH) + e];
    }
}

// ---------------------------------------------------------------------------
// Phase 3: O_c = Q_c @ M_c (3xTF32) + mask(Q_c K_c^T) @ V_c (tf32).
// Output rounded to tf32 (the final GEMM does no conversion).
// ---------------------------------------------------------------------------
__global__ void __launch_bounds__(128) attn_chunk() {
    extern __shared__ float sm3[];
    float* Qs = sm3;
    float* Ks = Qs + 64 * 68;
    float* Vs = Ks + 64 * 68;
    float* Ms = Vs + 64 * 68;
    float* Ss = Ms + 64 * 68;

    const int ch = blockIdx.x, bh = blockIdx.y;
    const int b = bh >> 4, h = bh & 15;
    const int t0 = ch * CH;
    const int tid = threadIdx.x, w = tid >> 5, lane = tid & 31;

    const float* Qg = g_q + (size_t)(b * T_ + t0) * DM + h * DH;
    const float* Kg = g_k + (size_t)(b * T_ + t0) * DM + h * DH;
    const float* Vg = g_v + (size_t)(b * T_ + t0) * DM + h * DH;
    const float* Mg = g_m + ((size_t)bh * NCH + ch) * DH * DH;

#pragma unroll
    for (int i = 0; i < 8; i++) {
        int id = tid + i * 128;
        int r = id >> 4, c = (id & 15) * 4;
        *(float4*)(Qs + r * 68 + c) = *(const float4*)(Qg + (size_t)r * DM + c);
        *(float4*)(Ks + r * 68 + c) = *(const float4*)(Kg + (size_t)r * DM + c);
        *(float4*)(Vs + r * 68 + c) = *(const float4*)(Vg + (size_t)r * DM + c);
        *(float4*)(Ms + r * 68 + c) = *(const float4*)(Mg + id * 4);
    }
    __syncthreads();

    wmma::fragment<wmma::accumulator, 16, 16, 8, float> o[4];
#pragma unroll
    for (int i = 0; i < 4; i++) wmma::fill_fragment(o[i], 0.0f);

    // (a) O = Q @ M  with 3xTF32
#pragma unroll
    for (int kk = 0; kk < 8; kk++) {
        wmma::fragment<wmma::matrix_a, 16, 16, 8, wmma::precision::tf32, wmma::row_major> ah, al;
        wmma::load_matrix_sync(ah, Qs + (w * 16) * 68 + kk * 8, 68);
#pragma unroll
        for (int e = 0; e < ah.num_elements; e++) {
            float x = ah.x[e];
            float hi = wmma::__float_to_tf32(x);
            ah.x[e] = hi;
            al.x[e] = wmma::__float_to_tf32(x - hi);
        }
#pragma unroll
        for (int nf = 0; nf < 4; nf++) {
            wmma::fragment<wmma::matrix_b, 16, 16, 8, wmma::precision::tf32, wmma::row_major> bhi, blo;
            wmma::load_matrix_sync(bhi, Ms + (kk * 8) * 68 + nf * 16, 68);
#pragma unroll
            for (int e = 0; e < bhi.num_elements; e++) {
                float x = bhi.x[e];
                float hi = wmma::__float_to_tf32(x);
                bhi.x[e] = hi;
                blo.x[e] = wmma::__float_to_tf32(x - hi);
            }
            wmma::mma_sync(o[nf], ah, bhi, o[nf]);
            wmma::mma_sync(o[nf], ah, blo, o[nf]);
            wmma::mma_sync(o[nf], al, bhi, o[nf]);
        }
    }

    // (b) S = Q @ K^T
    wmma::fragment<wmma::accumulator, 16, 16, 8, float> s_acc[4];
#pragma unroll
    for (int i = 0; i < 4; i++) wmma::fill_fragment(s_acc[i], 0.0f);
#pragma unroll
    for (int kk = 0; kk < 8; kk++) {
        wmma::fragment<wmma::matrix_a, 16, 16, 8, wmma::precision::tf32, wmma::row_major> a;
        wmma::load_matrix_sync(a, Qs + (w * 16) * 68 + kk * 8, 68);
#pragma unroll
        for (int e = 0; e < a.num_elements; e++) a.x[e] = wmma::__float_to_tf32(a.x[e]);
#pragma unroll
        for (int nf = 0; nf < 4; nf++) {
            wmma::fragment<wmma::matrix_b, 16, 16, 8, wmma::precision::tf32, wmma::col_major> bb;
            wmma::load_matrix_sync(bb, Ks + (nf * 16) * 68 + kk * 8, 68);
#pragma unroll
            for (int e = 0; e < bb.num_elements; e++) bb.x[e] = wmma::__float_to_tf32(bb.x[e]);
            wmma::mma_sync(s_acc[nf], a, bb, s_acc[nf]);
        }
    }
#pragma unroll
    for (int nf = 0; nf < 4; nf++)
        wmma::store_matrix_sync(Ss + (w * 16) * 68 + nf * 16, s_acc[nf], 68,
                                wmma::mem_row_major);
    __syncwarp();

#pragma unroll
    for (int i = 0; i < 32; i++) {
        int e = i * 32 + lane;
        int r = e >> 6, c = e & 63;
        if (c >= w * 16 + r) Ss[(w * 16 + r) * 68 + c] = 0.0f;
    }
    __syncwarp();

    // (c) O += S @ V
#pragma unroll
    for (int kk = 0; kk < 8; kk++) {
        wmma::fragment<wmma::matrix_a, 16, 16, 8, wmma::precision::tf32, wmma::row_major> a;
        wmma::load_matrix_sync(a, Ss + (w * 16) * 68 + kk * 8, 68);
#pragma unroll
        for (int e = 0; e < a.num_elements; e++) a.x[e] = wmma::__float_to_tf32(a.x[e]);
#pragma unroll
        for (int nf = 0; nf < 4; nf++) {
            wmma::fragment<wmma::matrix_b, 16, 16, 8, wmma::precision::tf32, wmma::row_major> bb;
            wmma::load_matrix_sync(bb, Vs + (kk * 8) * 68 + nf * 16, 68);
#pragma unroll
            for (int e = 0; e < bb.num_elements; e++) bb.x[e] = wmma::__float_to_tf32(bb.x[e]);
            wmma::mma_sync(o[nf], a, bb, o[nf]);
        }
    }

    // Round output to exact tf32 for the conversion-free final GEMM
    float* Og = g_attn + (size_t)(b * T_ + t0 + w * 16) * DM + h * DH;
#pragma unroll
    for (int nf = 0; nf < 4; nf++) {
#pragma unroll
        for (int e = 0; e < o[nf].num_elements; e++)
            o[nf].x[e] = wmma::__float_to_tf32(o[nf].x[e]);
        wmma::store_matrix_sync(Og + nf * 16, o[nf], DM, wmma::mem_row_major);
    }
}

// ---------------------------------------------------------------------------
extern "C" void kernel_launch(void* const* d_in, const int* in_sizes, int n_in,
                              void* d_out, int out_size) {
    const float* x  = (const float*)d_in[0];
    const float* Wq = (const float*)d_in[1];
    const float* Wk = (const float*)d_in[2];
    const float* Wv = (const float*)d_in[3];
    const float* Wo = (const float*)d_in[4];

    float *q, *k, *v, *attn, *xr, *wr;
    cudaGetSymbolAddress((void**)&q,    g_q);
    cudaGetSymbolAddress((void**)&k,    g_k);
    cudaGetSymbolAddress((void**)&v,    g_v);
    cudaGetSymbolAddress((void**)&attn, g_attn);
    cudaGetSymbolAddress((void**)&xr,   g_xr);
    cudaGetSymbolAddress((void**)&wr,   g_wr);

    constexpr int GEMM_SMEM = (2 * 128 * LDA + 2 * 32 * LDB) * 4;   // 70656
    constexpr int ATTN_SMEM = 5 * 64 * 68 * 4;                      // 87040
    cudaFuncSetAttribute(gemm_tf32, cudaFuncAttributeMaxDynamicSharedMemorySize, GEMM_SMEM);
    cudaFuncSetAttribute(attn_chunk, cudaFuncAttributeMaxDynamicSharedMemorySize, ATTN_SMEM);

    // Pre-round all GEMM operands to exact tf32
    round_buf<<<ROWS * DM / 4 / 256, 256>>>((const float4*)x, (float4*)xr);
    round_buf<<<DM * DM / 4 / 256, 256>>>((const float4*)Wq, (float4*)(wr + 0 * DM * DM));
    round_buf<<<DM * DM / 4 / 256, 256>>>((const float4*)Wk, (float4*)(wr + 1 * DM * DM));
    round_buf<<<DM * DM / 4 / 256, 256>>>((const float4*)Wv, (float4*)(wr + 2 * DM * DM));
    round_buf<<<DM * DM / 4 / 256, 256>>>((const float4*)Wo, (float4*)(wr + 3 * DM * DM));

    dim3 gg(GN / 128, ROWS / 128);   // (8, 32)
    gemm_tf32<<<gg, 256, GEMM_SMEM>>>(xr, wr + 0 * DM * DM, q);
    gemm_tf32<<<gg, 256, GEMM_SMEM>>>(xr, wr + 1 * DM * DM, k);
    gemm_tf32<<<gg, 256, GEMM_SMEM>>>(xr, wr + 2 * DM * DM, v);

    chunk_kv<<<dim3(NCH, BH), 128>>>();
    prefix_kv<<<dim3(8, BH), 512>>>();
    attn_chunk<<<dim3(NCH, BH), 128, ATTN_SMEM>>>();

    gemm_tf32<<<gg, 256, GEMM_SMEM>>>(attn, wr + 3 * DM * DM, (float*)d_out);
}

// round 6
// speedup vs baseline: 2.0780x; 1.2578x over previous
#include <cuda_runtime.h>
#include <cuda_bf16.h>
#include <mma.h>
#include <cstdint>
using namespace nvcuda;

#define B_   2
#define T_   2048
#define DM   1024
#define H_   16
#define DH   64
#define ROWS (B_*T_)       // 4096
#define CH   64
#define NCH  (T_/CH)       // 32
#define BH   (B_*H_)       // 32
#define GN   1024
#define GK   1024

// Scratch (allocation-free rule -> __device__ globals)
__device__ float g_q[ROWS*DM];
__device__ float g_k[ROWS*DM];
__device__ float g_v[ROWS*DM];
__device__ float g_kv[(size_t)BH*NCH*DH*DH];
__device__ float g_m [(size_t)BH*NCH*DH*DH];
__device__ __nv_bfloat16 g_xhi[ROWS*DM], g_xlo[ROWS*DM];
__device__ __nv_bfloat16 g_whi[4*DM*DM], g_wlo[4*DM*DM];
__device__ __nv_bfloat16 g_ahi[ROWS*DM], g_alo[ROWS*DM];

__device__ __forceinline__ void cp16f(float* dst, const float* src) {
    uint32_t d = (uint32_t)__cvta_generic_to_shared(dst);
    asm volatile("cp.async.cg.shared.global [%0], [%1], 16;\n" :: "r"(d), "l"(src));
}
__device__ __forceinline__ void cp16b(__nv_bfloat16* dst, const __nv_bfloat16* src) {
    uint32_t d = (uint32_t)__cvta_generic_to_shared(dst);
    asm volatile("cp.async.cg.shared.global [%0], [%1], 16;\n" :: "r"(d), "l"(src));
}

// ---------------------------------------------------------------------------
// Prepass: split fp32 buffer into bf16 hi/lo pair (8 floats per thread).
// ---------------------------------------------------------------------------
__global__ void __launch_bounds__(256) split_buf(const float4* __restrict__ src,
                                                 uint4* __restrict__ hi,
                                                 uint4* __restrict__ lo) {
    int i = blockIdx.x * 256 + threadIdx.x;
    float4 a = src[2 * i], b = src[2 * i + 1];
    float v[8] = {a.x, a.y, a.z, a.w, b.x, b.y, b.z, b.w};
    __nv_bfloat16 h[8], l[8];
#pragma unroll
    for (int j = 0; j < 8; j++) {
        h[j] = __float2bfloat16(v[j]);
        l[j] = __float2bfloat16(v[j] - __bfloat162float(h[j]));
    }
    hi[i] = *(uint4*)h;
    lo[i] = *(uint4*)l;
}

// ---------------------------------------------------------------------------
// bf16x3 GEMM: C = (Ahi+Alo)@(Bhi+Blo) ~ hh + hl + lh, fp32 accumulate.
// Block tile 128x128, ktile 32 (2 k-steps of 16), 8 warps (32x64 warp tiles),
// cp.async double buffering. All fragment loads are LDSM.
// ---------------------------------------------------------------------------
#define LDAb 40     // 128 x 32 bf16, padded
#define LDBb 136    // 32 x 128 bf16, padded
#define ASZ  (128*LDAb)   // 5120 elems per buffer
#define BSZ  (32*LDBb)    // 4352 elems per buffer
#define GEMM_SMEM ((4*ASZ + 4*BSZ) * 2)   // bytes = 75776

typedef wmma::fragment<wmma::matrix_a, 16, 16, 16, __nv_bfloat16, wmma::row_major> FragA;
typedef wmma::fragment<wmma::matrix_b, 16, 16, 16, __nv_bfloat16, wmma::row_major> FragB;

__global__ void __launch_bounds__(256) gemm_bf16x3(const __nv_bfloat16* __restrict__ Ahi,
                                                   const __nv_bfloat16* __restrict__ Alo,
                                                   const __nv_bfloat16* __restrict__ Bhi,
                                                   const __nv_bfloat16* __restrict__ Blo,
                                                   float* __restrict__ C) {
    extern __shared__ __nv_bfloat16 smb[];
    __nv_bfloat16* sAH = smb;                 // 2 x ASZ
    __nv_bfloat16* sAL = smb + 2 * ASZ;
    __nv_bfloat16* sBH = smb + 4 * ASZ;       // 2 x BSZ
    __nv_bfloat16* sBL = smb + 4 * ASZ + 2 * BSZ;

    const int row0 = blockIdx.y * 128;
    const int col0 = blockIdx.x * 128;
    const int tid  = threadIdx.x;
    const int w    = tid >> 5;
    const int wr   = w & 3;                   // 4 row groups of 32
    const int wc   = w >> 2;                  // 2 col groups of 64

    wmma::fragment<wmma::accumulator, 16, 16, 16, float> acc[2][4];
#pragma unroll
    for (int i = 0; i < 2; i++)
#pragma unroll
        for (int j = 0; j < 4; j++) wmma::fill_fragment(acc[i][j], 0.0f);

    auto issue = [&](int kt, int buf) {
        const int k0 = kt * 32;
#pragma unroll
        for (int i = 0; i < 2; i++) {          // A: 128x32 = 512 cp16 per array
            int id = tid + i * 256;
            int r = id >> 2, c8 = (id & 3) * 8;
            cp16b(sAH + buf * ASZ + r * LDAb + c8, Ahi + (size_t)(row0 + r) * GK + k0 + c8);
            cp16b(sAL + buf * ASZ + r * LDAb + c8, Alo + (size_t)(row0 + r) * GK + k0 + c8);
        }
#pragma unroll
        for (int i = 0; i < 2; i++) {          // B: 32x128 = 512 cp16 per array
            int id = tid + i * 256;
            int r = id >> 4, c8 = (id & 15) * 8;
            cp16b(sBH + buf * BSZ + r * LDBb + c8, Bhi + (size_t)(k0 + r) * GN + col0 + c8);
            cp16b(sBL + buf * BSZ + r * LDBb + c8, Blo + (size_t)(k0 + r) * GN + col0 + c8);
        }
        asm volatile("cp.async.commit_group;\n");
    };

    issue(0, 0);
    const int NT = GK / 32;
    for (int kt = 0; kt < NT; kt++) {
        const int cur = kt & 1;
        if (kt + 1 < NT) {
            issue(kt + 1, cur ^ 1);
            asm volatile("cp.async.wait_group 1;\n");
        } else {
            asm volatile("cp.async.wait_group 0;\n");
        }
        __syncthreads();

        const __nv_bfloat16* Ah = sAH + cur * ASZ;
        const __nv_bfloat16* Al = sAL + cur * ASZ;
        const __nv_bfloat16* Bh = sBH + cur * BSZ;
        const __nv_bfloat16* Bl = sBL + cur * BSZ;
#pragma unroll
        for (int kk = 0; kk < 2; kk++) {
            FragA a_hi[2], a_lo[2];
#pragma unroll
            for (int i = 0; i < 2; i++) {
                wmma::load_matrix_sync(a_hi[i], Ah + (wr * 32 + i * 16) * LDAb + kk * 16, LDAb);
                wmma::load_matrix_sync(a_lo[i], Al + (wr * 32 + i * 16) * LDAb + kk * 16, LDAb);
            }
#pragma unroll
            for (int j = 0; j < 4; j++) {
                FragB b_h, b_l;
                wmma::load_matrix_sync(b_h, Bh + (kk * 16) * LDBb + wc * 64 + j * 16, LDBb);
                wmma::load_matrix_sync(b_l, Bl + (kk * 16) * LDBb + wc * 64 + j * 16, LDBb);
#pragma unroll
                for (int i = 0; i < 2; i++) {
                    wmma::mma_sync(acc[i][j], a_hi[i], b_h, acc[i][j]);
                    wmma::mma_sync(acc[i][j], a_hi[i], b_l, acc[i][j]);
                    wmma::mma_sync(acc[i][j], a_lo[i], b_h, acc[i][j]);
                }
            }
        }
        __syncthreads();
    }

#pragma unroll
    for (int i = 0; i < 2; i++)
#pragma unroll
        for (int j = 0; j < 4; j++)
            wmma::store_matrix_sync(C + (size_t)(row0 + wr * 32 + i * 16) * GN
                                      + col0 + wc * 64 + j * 16,
                                    acc[i][j], GN, wmma::mem_row_major);
}

// ---------------------------------------------------------------------------
// Phase 1: per-chunk KV_c = K_c^T @ V_c  (64x64, k-dim 64), 3xTF32.
// ---------------------------------------------------------------------------
__global__ void __launch_bounds__(128) chunk_kv() {
    __shared__ float Ks[CH * 68];
    __shared__ float Vs[CH * 68];
    const int ch = blockIdx.x, bh = blockIdx.y;
    const int b = bh >> 4, h = bh & 15;
    const int tid = threadIdx.x, w = tid >> 5;

    const float* Kg = g_k + (size_t)(b * T_ + ch * CH) * DM + h * DH;
    const float* Vg = g_v + (size_t)(b * T_ + ch * CH) * DM + h * DH;
#pragma unroll
    for (int i = 0; i < 8; i++) {
        int id = tid + i * 128;
        int r = id >> 4, c = (id & 15) * 4;
        *(float4*)(Ks + r * 68 + c) = *(const float4*)(Kg + (size_t)r * DM + c);
        *(float4*)(Vs + r * 68 + c) = *(const float4*)(Vg + (size_t)r * DM + c);
    }
    __syncthreads();

    wmma::fragment<wmma::accumulator, 16, 16, 8, float> acc[4];
#pragma unroll
    for (int i = 0; i < 4; i++) wmma::fill_fragment(acc[i], 0.0f);

#pragma unroll
    for (int kk = 0; kk < 8; kk++) {
        wmma::fragment<wmma::matrix_a, 16, 16, 8, wmma::precision::tf32, wmma::col_major> ah, al;
        wmma::load_matrix_sync(ah, Ks + (kk * 8) * 68 + w * 16, 68);
#pragma unroll
        for (int e = 0; e < ah.num_elements; e++) {
            float x = ah.x[e];
            float hi = wmma::__float_to_tf32(x);
            ah.x[e] = hi;
            al.x[e] = wmma::__float_to_tf32(x - hi);
        }
#pragma unroll
        for (int nf = 0; nf < 4; nf++) {
            wmma::fragment<wmma::matrix_b, 16, 16, 8, wmma::precision::tf32, wmma::row_major> bhi, blo;
            wmma::load_matrix_sync(bhi, Vs + (kk * 8) * 68 + nf * 16, 68);
#pragma unroll
            for (int e = 0; e < bhi.num_elements; e++) {
                float x = bhi.x[e];
                float hi = wmma::__float_to_tf32(x);
                bhi.x[e] = hi;
                blo.x[e] = wmma::__float_to_tf32(x - hi);
            }
            wmma::mma_sync(acc[nf], ah, bhi, acc[nf]);
            wmma::mma_sync(acc[nf], ah, blo, acc[nf]);
            wmma::mma_sync(acc[nf], al, bhi, acc[nf]);
        }
    }

    float* out = g_kv + ((size_t)bh * NCH + ch) * DH * DH;
#pragma unroll
    for (int nf = 0; nf < 4; nf++)
        wmma::store_matrix_sync(out + (w * 16) * DH + nf * 16, acc[nf], DH,
                                wmma::mem_row_major);
}

// ---------------------------------------------------------------------------
// Phase 2: exclusive prefix over chunks (fp32 exact).
// ---------------------------------------------------------------------------
__global__ void __launch_bounds__(512) prefix_kv() {
    const int bh = blockIdx.y;
    const int e  = blockIdx.x * 512 + threadIdx.x;
    const size_t base = (size_t)bh * NCH * DH * DH;
    float run = 0.0f;
#pragma unroll
    for (int c = 0; c < NCH; c++) {
        g_m[base + (size_t)c * (DH * DH) + e] = run;
        run += g_kv[base + (size_t)c * (DH * DH) + e];
    }
}

// ---------------------------------------------------------------------------
// Phase 3: O_c = Q_c @ M_c (3xTF32) + mask(Q_c K_c^T) @ V_c (tf32).
// Epilogue writes bf16 hi/lo split directly for the final GEMM.
// ---------------------------------------------------------------------------
__global__ void __launch_bounds__(128) attn_chunk() {
    extern __shared__ float sm3[];
    float* Qs = sm3;
    float* Ks = Qs + 64 * 68;
    float* Vs = Ks + 64 * 68;
    float* Ms = Vs + 64 * 68;
    float* Ss = Ms + 64 * 68;

    const int ch = blockIdx.x, bh = blockIdx.y;
    const int b = bh >> 4, h = bh & 15;
    const int t0 = ch * CH;
    const int tid = threadIdx.x, w = tid >> 5, lane = tid & 31;

    const float* Qg = g_q + (size_t)(b * T_ + t0) * DM + h * DH;
    const float* Kg = g_k + (size_t)(b * T_ + t0) * DM + h * DH;
    const float* Vg = g_v + (size_t)(b * T_ + t0) * DM + h * DH;
    const float* Mg = g_m + ((size_t)bh * NCH + ch) * DH * DH;

#pragma unroll
    for (int i = 0; i < 8; i++) {
        int id = tid + i * 128;
        int r = id >> 4, c = (id & 15) * 4;
        *(float4*)(Qs + r * 68 + c) = *(const float4*)(Qg + (size_t)r * DM + c);
        *(float4*)(Ks + r * 68 + c) = *(const float4*)(Kg + (size_t)r * DM + c);
        *(float4*)(Vs + r * 68 + c) = *(const float4*)(Vg + (size_t)r * DM + c);
        *(float4*)(Ms + r * 68 + c) = *(const float4*)(Mg + id * 4);
    }
    __syncthreads();

    wmma::fragment<wmma::accumulator, 16, 16, 8, float> o[4];
#pragma unroll
    for (int i = 0; i < 4; i++) wmma::fill_fragment(o[i], 0.0f);

    // (a) O = Q @ M  with 3xTF32
#pragma unroll
    for (int kk = 0; kk < 8; kk++) {
        wmma::fragment<wmma::matrix_a, 16, 16, 8, wmma::precision::tf32, wmma::row_major> ah, al;
        wmma::load_matrix_sync(ah, Qs + (w * 16) * 68 + kk * 8, 68);
#pragma unroll
        for (int e = 0; e < ah.num_elements; e++) {
            float x = ah.x[e];
            float hi = wmma::__float_to_tf32(x);
            ah.x[e] = hi;
            al.x[e] = wmma::__float_to_tf32(x - hi);
        }
#pragma unroll
        for (int nf = 0; nf < 4; nf++) {
            wmma::fragment<wmma::matrix_b, 16, 16, 8, wmma::precision::tf32, wmma::row_major> bhi, blo;
            wmma::load_matrix_sync(bhi, Ms + (kk * 8) * 68 + nf * 16, 68);
#pragma unroll
            for (int e = 0; e < bhi.num_elements; e++) {
                float x = bhi.x[e];
                float hi = wmma::__float_to_tf32(x);
                bhi.x[e] = hi;
                blo.x[e] = wmma::__float_to_tf32(x - hi);
            }
            wmma::mma_sync(o[nf], ah, bhi, o[nf]);
            wmma::mma_sync(o[nf], ah, blo, o[nf]);
            wmma::mma_sync(o[nf], al, bhi, o[nf]);
        }
    }

    // (b) S = Q @ K^T
    wmma::fragment<wmma::accumulator, 16, 16, 8, float> s_acc[4];
#pragma unroll
    for (int i = 0; i < 4; i++) wmma::fill_fragment(s_acc[i], 0.0f);
#pragma unroll
    for (int kk = 0; kk < 8; kk++) {
        wmma::fragment<wmma::matrix_a, 16, 16, 8, wmma::precision::tf32, wmma::row_major> a;
        wmma::load_matrix_sync(a, Qs + (w * 16) * 68 + kk * 8, 68);
#pragma unroll
        for (int e = 0; e < a.num_elements; e++) a.x[e] = wmma::__float_to_tf32(a.x[e]);
#pragma unroll
        for (int nf = 0; nf < 4; nf++) {
            wmma::fragment<wmma::matrix_b, 16, 16, 8, wmma::precision::tf32, wmma::col_major> bb;
            wmma::load_matrix_sync(bb, Ks + (nf * 16) * 68 + kk * 8, 68);
#pragma unroll
            for (int e = 0; e < bb.num_elements; e++) bb.x[e] = wmma::__float_to_tf32(bb.x[e]);
            wmma::mma_sync(s_acc[nf], a, bb, s_acc[nf]);
        }
    }
#pragma unroll
    for (int nf = 0; nf < 4; nf++)
        wmma::store_matrix_sync(Ss + (w * 16) * 68 + nf * 16, s_acc[nf], 68,
                                wmma::mem_row_major);
    __syncwarp();

#pragma unroll
    for (int i = 0; i < 32; i++) {
        int e = i * 32 + lane;
        int r = e >> 6, c = e & 63;
        if (c >= w * 16 + r) Ss[(w * 16 + r) * 68 + c] = 0.0f;
    }
    __syncwarp();

    // (c) O += S @ V
#pragma unroll
    for (int kk = 0; kk < 8; kk++) {
        wmma::fragment<wmma::matrix_a, 16, 16, 8, wmma::precision::tf32, wmma::row_major> a;
        wmma::load_matrix_sync(a, Ss + (w * 16) * 68 + kk * 8, 68);
#pragma unroll
        for (int e = 0; e < a.num_elements; e++) a.x[e] = wmma::__float_to_tf32(a.x[e]);
#pragma unroll
        for (int nf = 0; nf < 4; nf++) {
            wmma::fragment<wmma::matrix_b, 16, 16, 8, wmma::precision::tf32, wmma::row_major> bb;
            wmma::load_matrix_sync(bb, Vs + (kk * 8) * 68 + nf * 16, 68);
#pragma unroll
            for (int e = 0; e < bb.num_elements; e++) bb.x[e] = wmma::__float_to_tf32(bb.x[e]);
            wmma::mma_sync(o[nf], a, bb, o[nf]);
        }
    }

    // Epilogue: dump O to smem, emit bf16 hi/lo split to global
#pragma unroll
    for (int nf = 0; nf < 4; nf++)
        wmma::store_matrix_sync(Ss + (w * 16) * 68 + nf * 16, o[nf], 68,
                                wmma::mem_row_major);
    __syncwarp();

    __nv_bfloat16* Hg = g_ahi + (size_t)(b * T_ + t0 + w * 16) * DM + h * DH;
    __nv_bfloat16* Lg = g_alo + (size_t)(b * T_ + t0 + w * 16) * DM + h * DH;
#pragma unroll
    for (int i = 0; i < 16; i++) {
#pragma unroll
        for (int c2 = 0; c2 < 2; c2++) {
            int c = c2 * 32 + lane;
            float xv = Ss[(w * 16 + i) * 68 + c];
            __nv_bfloat16 hb = __float2bfloat16(xv);
            Hg[(size_t)i * DM + c] = hb;
            Lg[(size_t)i * DM + c] = __float2bfloat16(xv - __bfloat162float(hb));
        }
    }
}

// ---------------------------------------------------------------------------
extern "C" void kernel_launch(void* const* d_in, const int* in_sizes, int n_in,
                              void* d_out, int out_size) {
    const float* x  = (const float*)d_in[0];
    const float* Wq = (const float*)d_in[1];
    const float* Wk = (const float*)d_in[2];
    const float* Wv = (const float*)d_in[3];
    const float* Wo = (const float*)d_in[4];

    float *q, *k, *v;
    __nv_bfloat16 *xhi, *xlo, *whi, *wlo, *ahi, *alo;
    cudaGetSymbolAddress((void**)&q,   g_q);
    cudaGetSymbolAddress((void**)&k,   g_k);
    cudaGetSymbolAddress((void**)&v,   g_v);
    cudaGetSymbolAddress((void**)&xhi, g_xhi);
    cudaGetSymbolAddress((void**)&xlo, g_xlo);
    cudaGetSymbolAddress((void**)&whi, g_whi);
    cudaGetSymbolAddress((void**)&wlo, g_wlo);
    cudaGetSymbolAddress((void**)&ahi, g_ahi);
    cudaGetSymbolAddress((void**)&alo, g_alo);

    constexpr int ATTN_SMEM = 5 * 64 * 68 * 4;   // 87040
    cudaFuncSetAttribute(gemm_bf16x3, cudaFuncAttributeMaxDynamicSharedMemorySize, GEMM_SMEM);
    cudaFuncSetAttribute(attn_chunk,  cudaFuncAttributeMaxDynamicSharedMemorySize, ATTN_SMEM);

    // Prepass: hi/lo bf16 splits of x and all weights
    split_buf<<<ROWS * DM / 8 / 256, 256>>>((const float4*)x, (uint4*)xhi, (uint4*)xlo);
    split_buf<<<DM * DM / 8 / 256, 256>>>((const float4*)Wq, (uint4*)(whi + 0 * DM * DM), (uint4*)(wlo + 0 * DM * DM));
    split_buf<<<DM * DM / 8 / 256, 256>>>((const float4*)Wk, (uint4*)(whi + 1 * DM * DM), (uint4*)(wlo + 1 * DM * DM));
    split_buf<<<DM * DM / 8 / 256, 256>>>((const float4*)Wv, (uint4*)(whi + 2 * DM * DM), (uint4*)(wlo + 2 * DM * DM));
    split_buf<<<DM * DM / 8 / 256, 256>>>((const float4*)Wo, (uint4*)(whi + 3 * DM * DM), (uint4*)(wlo + 3 * DM * DM));

    dim3 gg(GN / 128, ROWS / 128);   // (8, 32)
    gemm_bf16x3<<<gg, 256, GEMM_SMEM>>>(xhi, xlo, whi + 0 * DM * DM, wlo + 0 * DM * DM, q);
    gemm_bf16x3<<<gg, 256, GEMM_SMEM>>>(xhi, xlo, whi + 1 * DM * DM, wlo + 1 * DM * DM, k);
    gemm_bf16x3<<<gg, 256, GEMM_SMEM>>>(xhi, xlo, whi + 2 * DM * DM, wlo + 2 * DM * DM, v);

    chunk_kv<<<dim3(NCH, BH), 128>>>();
    prefix_kv<<<dim3(8, BH), 512>>>();
    attn_chunk<<<dim3(NCH, BH), 128, ATTN_SMEM>>>();

    gemm_bf16x3<<<gg, 256, GEMM_SMEM>>>(ahi, alo, whi + 3 * DM * DM, wlo + 3 * DM * DM, (float*)d_out);
}

// round 10
// speedup vs baseline: 4.0920x; 1.9692x over previous
#include <cuda_runtime.h>
#include <cuda_fp16.h>
#include <mma.h>
#include <cstdint>
using namespace nvcuda;

#define B_   2
#define T_   2048
#define DM   1024
#define H_   16
#define DH   64
#define ROWS (B_*T_)       // 4096
#define CH   64
#define NCH  (T_/CH)       // 32
#define BH   (B_*H_)       // 32
#define GN   1024
#define GK   1024

// Scratch (allocation-free rule -> __device__ globals)
__device__ __align__(16) __half g_qh[ROWS*DM];
__device__ __align__(16) __half g_kh[ROWS*DM];
__device__ __align__(16) __half g_vh[ROWS*DM];
__device__ __align__(16) __half g_ah[ROWS*DM];      // attention output (fp16)
__device__ __align__(16) __half g_xh[ROWS*DM];      // x in fp16
__device__ __align__(16) __half g_wh[4*DM*DM];      // Wq|Wk|Wv|Wo in fp16
__device__ float g_kv[(size_t)BH*NCH*DH*DH];
__device__ float g_m [(size_t)BH*NCH*DH*DH];

__device__ __forceinline__ void cp16h(__half* dst, const __half* src) {
    uint32_t d = (uint32_t)__cvta_generic_to_shared(dst);
    asm volatile("cp.async.cg.shared.global [%0], [%1], 16;\n" :: "r"(d), "l"(src));
}

// ---------------------------------------------------------------------------
// Prepass: fp32 -> fp16 (8 elems per thread).
// ---------------------------------------------------------------------------
__global__ void __launch_bounds__(256) tofp16(const float4* __restrict__ src,
                                              uint4* __restrict__ dst) {
    int i = blockIdx.x * 256 + threadIdx.x;
    float4 a = src[2 * i], b = src[2 * i + 1];
    __half h[8] = {__float2half_rn(a.x), __float2half_rn(a.y),
                   __float2half_rn(a.z), __float2half_rn(a.w),
                   __float2half_rn(b.x), __float2half_rn(b.y),
                   __float2half_rn(b.z), __float2half_rn(b.w)};
    dst[i] = *(uint4*)h;
}

// ---------------------------------------------------------------------------
// fp16 GEMM, fp32 accumulate: C[M,N] = A[M,K] @ W[K,N].
// Block tile 128x128, ktile 64, 8 warps (32x64 warp tiles), double buffered.
// HALF_OUT: stage in smem, emit fp16. Else emit fp32 directly.
// ---------------------------------------------------------------------------
#define LDAh 72     // 64 + 8 pad (halves)
#define LDBh 136    // 128 + 8 pad (halves)
#define ASZh (128*LDAh)
#define BSZh (64*LDBh)
#define GEMM_SMEM ((2*ASZh + 2*BSZh) * 2)   // 71680 B

typedef wmma::fragment<wmma::matrix_a, 16, 16, 16, __half, wmma::row_major> HFragA;
typedef wmma::fragment<wmma::matrix_b, 16, 16, 16, __half, wmma::row_major> HFragB;

template <bool HALF_OUT>
__global__ void __launch_bounds__(256) gemm_h(const __half* __restrict__ A,
                                              const __half* __restrict__ W,
                                              void* __restrict__ Cv) {
    extern __shared__ __half smb[];
    __half* sA = smb;                // 2 x ASZh
    __half* sB = smb + 2 * ASZh;     // 2 x BSZh

    const int row0 = blockIdx.y * 128;
    const int col0 = blockIdx.x * 128;
    const int tid  = threadIdx.x;
    const int w    = tid >> 5;
    const int wr   = w & 3;          // 4 row groups of 32
    const int wc   = w >> 2;         // 2 col groups of 64

    wmma::fragment<wmma::accumulator, 16, 16, 16, float> acc[2][4];
#pragma unroll
    for (int i = 0; i < 2; i++)
#pragma unroll
        for (int j = 0; j < 4; j++) wmma::fill_fragment(acc[i][j], 0.0f);

    auto issue = [&](int kt, int buf) {
        const int k0 = kt * 64;
#pragma unroll
        for (int i = 0; i < 4; i++) {           // A: 128x64 halves = 1024 cp16
            int id = tid + i * 256;
            int r = id >> 3, c8 = (id & 7) * 8;
            cp16h(sA + buf * ASZh + r * LDAh + c8, A + (size_t)(row0 + r) * GK + k0 + c8);
        }
#pragma unroll
        for (int i = 0; i < 4; i++) {           // B: 64x128 halves = 1024 cp16
            int id = tid + i * 256;
            int r = id >> 4, c8 = (id & 15) * 8;
            cp16h(sB + buf * BSZh + r * LDBh + c8, W + (size_t)(k0 + r) * GN + col0 + c8);
        }
        asm volatile("cp.async.commit_group;\n");
    };

    issue(0, 0);
    const int NT = GK / 64;          // 16
    for (int kt = 0; kt < NT; kt++) {
        const int cur = kt & 1;
        if (kt + 1 < NT) {
            issue(kt + 1, cur ^ 1);
            asm volatile("cp.async.wait_group 1;\n");
        } else {
            asm volatile("cp.async.wait_group 0;\n");
        }
        __syncthreads();

        const __half* Ac = sA + cur * ASZh;
        const __half* Bc = sB + cur * BSZh;
#pragma unroll
        for (int kk = 0; kk < 4; kk++) {
            HFragA a[2];
#pragma unroll
            for (int i = 0; i < 2; i++)
                wmma::load_matrix_sync(a[i], Ac + (wr * 32 + i * 16) * LDAh + kk * 16, LDAh);
#pragma unroll
            for (int j = 0; j < 4; j++) {
                HFragB b;
                wmma::load_matrix_sync(b, Bc + (kk * 16) * LDBh + wc * 64 + j * 16, LDBh);
#pragma unroll
                for (int i = 0; i < 2; i++)
                    wmma::mma_sync(acc[i][j], a[i], b, acc[i][j]);
            }
        }
        __syncthreads();
    }

    if constexpr (HALF_OUT) {
        float* st = (float*)smb;     // 128 x 132 staging (67584 B <= GEMM_SMEM)
#pragma unroll
        for (int i = 0; i < 2; i++)
#pragma unroll
            for (int j = 0; j < 4; j++)
                wmma::store_matrix_sync(st + (wr * 32 + i * 16) * 132 + wc * 64 + j * 16,
                                        acc[i][j], 132, wmma::mem_row_major);
        __syncthreads();
        __half* C = (__half*)Cv;
#pragma unroll
        for (int i = 0; i < 8; i++) {          // 128x128 halves = 2048 uint4
            int id = tid + i * 256;
            int r = id >> 4, c8 = (id & 15) * 8;
            __half h[8];
#pragma unroll
            for (int e = 0; e < 8; e++) h[e] = __float2half_rn(st[r * 132 + c8 + e]);
            *(uint4*)(C + (size_t)(row0 + r) * GN + col0 + c8) = *(uint4*)h;
        }
    } else {
        float* C = (float*)Cv;
#pragma unroll
        for (int i = 0; i < 2; i++)
#pragma unroll
            for (int j = 0; j < 4; j++)
                wmma::store_matrix_sync(C + (size_t)(row0 + wr * 32 + i * 16) * GN
                                          + col0 + wc * 64 + j * 16,
                                        acc[i][j], GN, wmma::mem_row_major);
    }
}

// ---------------------------------------------------------------------------
// Phase 1: per-chunk KV_c = K_c^T @ V_c (64x64, k=64), fp16 in / fp32 acc.
// ---------------------------------------------------------------------------
__global__ void __launch_bounds__(128) chunk_kv() {
    __shared__ __half Ks[CH * LDAh];
    __shared__ __half Vs[CH * LDAh];
    const int ch = blockIdx.x, bh = blockIdx.y;
    const int b = bh >> 4, h = bh & 15;
    const int tid = threadIdx.x, w = tid >> 5;

    const __half* Kg = g_kh + (size_t)(b * T_ + ch * CH) * DM + h * DH;
    const __half* Vg = g_vh + (size_t)(b * T_ + ch * CH) * DM + h * DH;
#pragma unroll
    for (int i = 0; i < 4; i++) {              // 64x64 halves = 512 uint4 each
        int id = tid + i * 128;
        int r = id >> 3, c8 = (id & 7) * 8;
        *(uint4*)(Ks + r * LDAh + c8) = *(const uint4*)(Kg + (size_t)r * DM + c8);
        *(uint4*)(Vs + r * LDAh + c8) = *(const uint4*)(Vg + (size_t)r * DM + c8);
    }
    __syncthreads();

    wmma::fragment<wmma::accumulator, 16, 16, 16, float> acc[4];
#pragma unroll
    for (int i = 0; i < 4; i++) wmma::fill_fragment(acc[i], 0.0f);

#pragma unroll
    for (int kk = 0; kk < 4; kk++) {           // s-dimension in steps of 16
        wmma::fragment<wmma::matrix_a, 16, 16, 16, __half, wmma::col_major> a;
        wmma::load_matrix_sync(a, Ks + (kk * 16) * LDAh + w * 16, LDAh);
#pragma unroll
        for (int nf = 0; nf < 4; nf++) {
            HFragB bb;
            wmma::load_matrix_sync(bb, Vs + (kk * 16) * LDAh + nf * 16, LDAh);
            wmma::mma_sync(acc[nf], a, bb, acc[nf]);
        }
    }

    float* out = g_kv + ((size_t)bh * NCH + ch) * DH * DH;
#pragma unroll
    for (int nf = 0; nf < 4; nf++)
        wmma::store_matrix_sync(out + (w * 16) * DH + nf * 16, acc[nf], DH,
                                wmma::mem_row_major);
}

// ---------------------------------------------------------------------------
// Phase 2: exclusive prefix over chunks (fp32 exact).
// ---------------------------------------------------------------------------
__global__ void __launch_bounds__(512) prefix_kv() {
    const int bh = blockIdx.y;
    const int e  = blockIdx.x * 512 + threadIdx.x;
    const size_t base = (size_t)bh * NCH * DH * DH;
    float run = 0.0f;
#pragma unroll
    for (int c = 0; c < NCH; c++) {
        g_m[base + (size_t)c * (DH * DH) + e] = run;
        run += g_kv[base + (size_t)c * (DH * DH) + e];
    }
}

// ---------------------------------------------------------------------------
// Phase 3: O_c = Q_c @ M_c + mask(Q_c K_c^T) @ V_c, all fp16 MMA / fp32 acc.
// ---------------------------------------------------------------------------
#define ATTN_SMEM (5 * 64 * LDAh * 2 + 64 * 68 * 4)   // 63488 B

__global__ void __launch_bounds__(128) attn_chunk() {
    extern __shared__ __half smh[];
    __half* Qs = smh;                 // 64 x 72 halves each
    __half* Ks = Qs + 64 * LDAh;
    __half* Vs = Ks + 64 * LDAh;
    __half* Ms = Vs + 64 * LDAh;
    __half* Sh = Ms + 64 * LDAh;
    float*  Ss = (float*)(Sh + 64 * LDAh);   // 64 x 68 fp32

    const int ch = blockIdx.x, bh = blockIdx.y;
    const int b = bh >> 4, h = bh & 15;
    const int t0 = ch * CH;
    const int tid = threadIdx.x, w = tid >> 5, lane = tid & 31;

    const __half* Qg = g_qh + (size_t)(b * T_ + t0) * DM + h * DH;
    const __half* Kg = g_kh + (size_t)(b * T_ + t0) * DM + h * DH;
    const __half* Vg = g_vh + (size_t)(b * T_ + t0) * DM + h * DH;
    const float*  Mg = g_m + ((size_t)bh * NCH + ch) * DH * DH;

#pragma unroll
    for (int i = 0; i < 4; i++) {             // Q,K,V: 512 uint4 each
        int id = tid + i * 128;
        int r = id >> 3, c8 = (id & 7) * 8;
        *(uint4*)(Qs + r * LDAh + c8) = *(const uint4*)(Qg + (size_t)r * DM + c8);
        *(uint4*)(Ks + r * LDAh + c8) = *(const uint4*)(Kg + (size_t)r * DM + c8);
        *(uint4*)(Vs + r * LDAh + c8) = *(const uint4*)(Vg + (size_t)r * DM + c8);
    }
#pragma unroll
    for (int i = 0; i < 8; i++) {             // M: 64x64 fp32 -> fp16 smem
        int id = tid + i * 128;
        int r = id >> 4, c4 = (id & 15) * 4;
        float4 mv = *(const float4*)(Mg + id * 4);
        __half hm[4] = {__float2half_rn(mv.x), __float2half_rn(mv.y),
                        __float2half_rn(mv.z), __float2half_rn(mv.w)};
        *(uint2*)(Ms + r * LDAh + c4) = *(uint2*)hm;
    }
    __syncthreads();

    wmma::fragment<wmma::accumulator, 16, 16, 16, float> o[4];
#pragma unroll
    for (int i = 0; i < 4; i++) wmma::fill_fragment(o[i], 0.0f);

    // (a) O = Q @ M
#pragma unroll
    for (int kk = 0; kk < 4; kk++) {
        HFragA a;
        wmma::load_matrix_sync(a, Qs + (w * 16) * LDAh + kk * 16, LDAh);
#pragma unroll
        for (int nf = 0; nf < 4; nf++) {
            HFragB bb;
            wmma::load_matrix_sync(bb, Ms + (kk * 16) * LDAh + nf * 16, LDAh);
            wmma::mma_sync(o[nf], a, bb, o[nf]);
        }
    }

    // (b) S = Q @ K^T
    wmma::fragment<wmma::accumulator, 16, 16, 16, float> s_acc[4];
#pragma unroll
    for (int i = 0; i < 4; i++) wmma::fill_fragment(s_acc[i], 0.0f);
#pragma unroll
    for (int kk = 0; kk < 4; kk++) {
        HFragA a;
        wmma::load_matrix_sync(a, Qs + (w * 16) * LDAh + kk * 16, LDAh);
#pragma unroll
        for (int nf = 0; nf < 4; nf++) {
            wmma::fragment<wmma::matrix_b, 16, 16, 16, __half, wmma::col_major> bb;
            wmma::load_matrix_sync(bb, Ks + (nf * 16) * LDAh + kk * 16, LDAh);
            wmma::mma_sync(s_acc[nf], a, bb, s_acc[nf]);
        }
    }
#pragma unroll
    for (int nf = 0; nf < 4; nf++)
        wmma::store_matrix_sync(Ss + (w * 16) * 68 + nf * 16, s_acc[nf], 68,
                                wmma::mem_row_major);
    __syncwarp();

    // strictly-lower mask (keep col < row) + fp16 convert
#pragma unroll
    for (int i = 0; i < 16; i++) {
#pragma unroll
        for (int c2 = 0; c2 < 2; c2++) {
            int c = c2 * 32 + lane;
            float v = (c < w * 16 + i) ? Ss[(w * 16 + i) * 68 + c] : 0.0f;
            Sh[(w * 16 + i) * LDAh + c] = __float2half_rn(v);
        }
    }
    __syncwarp();

    // (c) O += S @ V
#pragma unroll
    for (int kk = 0; kk < 4; kk++) {
        HFragA a;
        wmma::load_matrix_sync(a, Sh + (w * 16) * LDAh + kk * 16, LDAh);
#pragma unroll
        for (int nf = 0; nf < 4; nf++) {
            HFragB bb;
            wmma::load_matrix_sync(bb, Vs + (kk * 16) * LDAh + nf * 16, LDAh);
            wmma::mma_sync(o[nf], a, bb, o[nf]);
        }
    }

    // Epilogue: O -> fp16 global
#pragma unroll
    for (int nf = 0; nf < 4; nf++)
        wmma::store_matrix_sync(Ss + (w * 16) * 68 + nf * 16, o[nf], 68,
                                wmma::mem_row_major);
    __syncwarp();

    __half* Hg = g_ah + (size_t)(b * T_ + t0 + w * 16) * DM + h * DH;
#pragma unroll
    for (int i = 0; i < 16; i++) {
#pragma unroll
        for (int c2 = 0; c2 < 2; c2++) {
            int c = c2 * 32 + lane;
            Hg[(size_t)i * DM + c] = __float2half_rn(Ss[(w * 16 + i) * 68 + c]);
        }
    }
}

// ---------------------------------------------------------------------------
extern "C" void kernel_launch(void* const* d_in, const int* in_sizes, int n_in,
                              void* d_out, int out_size) {
    const float* x  = (const float*)d_in[0];
    const float* Wq = (const float*)d_in[1];
    const float* Wk = (const float*)d_in[2];
    const float* Wv = (const float*)d_in[3];
    const float* Wo = (const float*)d_in[4];

    __half *qh, *kh, *vh, *ah, *xh, *wh;
    cudaGetSymbolAddress((void**)&qh, g_qh);
    cudaGetSymbolAddress((void**)&kh, g_kh);
    cudaGetSymbolAddress((void**)&vh, g_vh);
    cudaGetSymbolAddress((void**)&ah, g_ah);
    cudaGetSymbolAddress((void**)&xh, g_xh);
    cudaGetSymbolAddress((void**)&wh, g_wh);

    cudaFuncSetAttribute(gemm_h<true>,  cudaFuncAttributeMaxDynamicSharedMemorySize, GEMM_SMEM);
    cudaFuncSetAttribute(gemm_h<false>, cudaFuncAttributeMaxDynamicSharedMemorySize, GEMM_SMEM);
    cudaFuncSetAttribute(attn_chunk,    cudaFuncAttributeMaxDynamicSharedMemorySize, ATTN_SMEM);

    // Prepass: fp16 conversions
    tofp16<<<ROWS * DM / 8 / 256, 256>>>((const float4*)x, (uint4*)xh);
    tofp16<<<DM * DM / 8 / 256, 256>>>((const float4*)Wq, (uint4*)(wh + 0 * DM * DM));
    tofp16<<<DM * DM / 8 / 256, 256>>>((const float4*)Wk, (uint4*)(wh + 1 * DM * DM));
    tofp16<<<DM * DM / 8 / 256, 256>>>((const float4*)Wv, (uint4*)(wh + 2 * DM * DM));
    tofp16<<<DM * DM / 8 / 256, 256>>>((const float4*)Wo, (uint4*)(wh + 3 * DM * DM));

    dim3 gg(GN / 128, ROWS / 128);   // (8, 32)
    gemm_h<true><<<gg, 256, GEMM_SMEM>>>(xh, wh + 0 * DM * DM, qh);
    gemm_h<true><<<gg, 256, GEMM_SMEM>>>(xh, wh + 1 * DM * DM, kh);
    gemm_h<true><<<gg, 256, GEMM_SMEM>>>(xh, wh + 2 * DM * DM, vh);

    chunk_kv<<<dim3(NCH, BH), 128>>>();
    prefix_kv<<<dim3(8, BH), 512>>>();
    attn_chunk<<<dim3(NCH, BH), 128, ATTN_SMEM>>>();

    gemm_h<false><<<gg, 256, GEMM_SMEM>>>(ah, wh + 3 * DM * DM, (float*)d_out);
}

// round 13
// speedup vs baseline: 6.2066x; 1.5168x over previous
#include <cuda_runtime.h>
#include <cuda_fp16.h>
#include <mma.h>
#include <cstdint>
using namespace nvcuda;

#define B_   2
#define T_   2048
#define DM   1024
#define H_   16
#define DH   64
#define ROWS (B_*T_)       // 4096
#define CH   64
#define NCH  (T_/CH)       // 32
#define BH   (B_*H_)       // 32
#define GK   1024
#define NQKV 3072          // fused q|k|v column dim

// Scratch (allocation-free rule -> __device__ globals)
__device__ __align__(16) __half g_xh[ROWS*DM];          // x fp16
__device__ __align__(16) __half g_wqkv[DM*NQKV];        // [k][3072] = Wq|Wk|Wv packed
__device__ __align__(16) __half g_woh[DM*DM];           // Wo fp16
__device__ __align__(16) __half g_qkv[(size_t)ROWS*NQKV]; // fused q|k|v output
__device__ __align__(16) __half g_ah[ROWS*DM];          // attention output fp16
__device__ float g_kv[(size_t)BH*NCH*DH*DH];
__device__ float g_m [(size_t)BH*NCH*DH*DH];

__device__ __forceinline__ void cp16h(__half* dst, const __half* src) {
    uint32_t d = (uint32_t)__cvta_generic_to_shared(dst);
    asm volatile("cp.async.cg.shared.global [%0], [%1], 16;\n" :: "r"(d), "l"(src));
}

// ---------------------------------------------------------------------------
// Prepass A: fp32 -> fp16, contiguous (8 elems / thread).
// ---------------------------------------------------------------------------
__global__ void __launch_bounds__(256) tofp16(const float4* __restrict__ src,
                                              uint4* __restrict__ dst) {
    int i = blockIdx.x * 256 + threadIdx.x;
    float4 a = src[2 * i], b = src[2 * i + 1];
    __half h[8] = {__float2half_rn(a.x), __float2half_rn(a.y),
                   __float2half_rn(a.z), __float2half_rn(a.w),
                   __float2half_rn(b.x), __float2half_rn(b.y),
                   __float2half_rn(b.z), __float2half_rn(b.w)};
    dst[i] = *(uint4*)h;
}

// ---------------------------------------------------------------------------
// Prepass B: convert + pack Wq|Wk|Wv into [k][3072]. grid (512, 3).
// ---------------------------------------------------------------------------
__global__ void __launch_bounds__(256) pack_qkv(const float4* __restrict__ Wq,
                                                const float4* __restrict__ Wk,
                                                const float4* __restrict__ Wv) {
    const int m = blockIdx.y;
    const float4* src = (m == 0) ? Wq : (m == 1) ? Wk : Wv;
    int i = blockIdx.x * 256 + threadIdx.x;          // i indexes 8-elem groups
    float4 a = src[2 * i], b = src[2 * i + 1];
    __half h[8] = {__float2half_rn(a.x), __float2half_rn(a.y),
                   __float2half_rn(a.z), __float2half_rn(a.w),
                   __float2half_rn(b.x), __float2half_rn(b.y),
                   __float2half_rn(b.z), __float2half_rn(b.w)};
    int e = i * 8;                                    // element index in [DM*DM)
    int kr = e >> 10, n = e & 1023;                   // row k, col n
    *(uint4*)(g_wqkv + (size_t)kr * NQKV + m * DM + n) = *(uint4*)h;
}

// ---------------------------------------------------------------------------
// fp16 GEMM, fp32 accumulate: C[M,NN] = A[M,GK] @ W[GK,NN].
// Block tile 128x128, ktile 64, 8 warps (32x64 warp tiles), double buffered.
// ---------------------------------------------------------------------------
#define LDAh 72     // 64 + 8 pad (halves)
#define LDBh 136    // 128 + 8 pad (halves)
#define ASZh (128*LDAh)
#define BSZh (64*LDBh)
#define GEMM_SMEM ((2*ASZh + 2*BSZh) * 2)   // 71680 B

typedef wmma::fragment<wmma::matrix_a, 16, 16, 16, __half, wmma::row_major> HFragA;
typedef wmma::fragment<wmma::matrix_b, 16, 16, 16, __half, wmma::row_major> HFragB;

template <int NN, bool HALF_OUT>
__global__ void __launch_bounds__(256) gemm_h(const __half* __restrict__ A,
                                              const __half* __restrict__ W,
                                              void* __restrict__ Cv) {
    extern __shared__ __half smb[];
    __half* sA = smb;                // 2 x ASZh
    __half* sB = smb + 2 * ASZh;     // 2 x BSZh

    const int row0 = blockIdx.y * 128;
    const int col0 = blockIdx.x * 128;
    const int tid  = threadIdx.x;
    const int w    = tid >> 5;
    const int wr   = w & 3;          // 4 row groups of 32
    const int wc   = w >> 2;         // 2 col groups of 64

    wmma::fragment<wmma::accumulator, 16, 16, 16, float> acc[2][4];
#pragma unroll
    for (int i = 0; i < 2; i++)
#pragma unroll
        for (int j = 0; j < 4; j++) wmma::fill_fragment(acc[i][j], 0.0f);

    auto issue = [&](int kt, int buf) {
        const int k0 = kt * 64;
#pragma unroll
        for (int i = 0; i < 4; i++) {           // A: 128x64 halves = 1024 cp16
            int id = tid + i * 256;
            int r = id >> 3, c8 = (id & 7) * 8;
            cp16h(sA + buf * ASZh + r * LDAh + c8, A + (size_t)(row0 + r) * GK + k0 + c8);
        }
#pragma unroll
        for (int i = 0; i < 4; i++) {           // B: 64x128 halves = 1024 cp16
            int id = tid + i * 256;
            int r = id >> 4, c8 = (id & 15) * 8;
            cp16h(sB + buf * BSZh + r * LDBh + c8, W + (size_t)(k0 + r) * NN + col0 + c8);
        }
        asm volatile("cp.async.commit_group;\n");
    };

    issue(0, 0);
    const int NT = GK / 64;          // 16
    for (int kt = 0; kt < NT; kt++) {
        const int cur = kt & 1;
        if (kt + 1 < NT) {
            issue(kt + 1, cur ^ 1);
            asm volatile("cp.async.wait_group 1;\n");
        } else {
            asm volatile("cp.async.wait_group 0;\n");
        }
        __syncthreads();

        const __half* Ac = sA + cur * ASZh;
        const __half* Bc = sB + cur * BSZh;
#pragma unroll
        for (int kk = 0; kk < 4; kk++) {
            HFragA a[2];
#pragma unroll
            for (int i = 0; i < 2; i++)
                wmma::load_matrix_sync(a[i], Ac + (wr * 32 + i * 16) * LDAh + kk * 16, LDAh);
#pragma unroll
            for (int j = 0; j < 4; j++) {
                HFragB b;
                wmma::load_matrix_sync(b, Bc + (kk * 16) * LDBh + wc * 64 + j * 16, LDBh);
#pragma unroll
                for (int i = 0; i < 2; i++)
                    wmma::mma_sync(acc[i][j], a[i], b, acc[i][j]);
            }
        }
        __syncthreads();
    }

    if constexpr (HALF_OUT) {
        float* st = (float*)smb;     // 128 x 132 staging (67584 B <= GEMM_SMEM)
#pragma unroll
        for (int i = 0; i < 2; i++)
#pragma unroll
            for (int j = 0; j < 4; j++)
                wmma::store_matrix_sync(st + (wr * 32 + i * 16) * 132 + wc * 64 + j * 16,
                                        acc[i][j], 132, wmma::mem_row_major);
        __syncthreads();
        __half* C = (__half*)Cv;
#pragma unroll
        for (int i = 0; i < 8; i++) {          // 128x128 halves = 2048 uint4
            int id = tid + i * 256;
            int r = id >> 4, c8 = (id & 15) * 8;
            __half h[8];
#pragma unroll
            for (int e = 0; e < 8; e++) h[e] = __float2half_rn(st[r * 132 + c8 + e]);
            *(uint4*)(C + (size_t)(row0 + r) * NN + col0 + c8) = *(uint4*)h;
        }
    } else {
        float* C = (float*)Cv;
#pragma unroll
        for (int i = 0; i < 2; i++)
#pragma unroll
            for (int j = 0; j < 4; j++)
                wmma::store_matrix_sync(C + (size_t)(row0 + wr * 32 + i * 16) * NN
                                          + col0 + wc * 64 + j * 16,
                                        acc[i][j], NN, wmma::mem_row_major);
    }
}

// ---------------------------------------------------------------------------
// Phase 1: per-chunk KV_c = K_c^T @ V_c (64x64, k=64), fp16 in / fp32 acc.
// Reads from fused qkv buffer (row stride NQKV; k at +DM, v at +2*DM).
// ---------------------------------------------------------------------------
__global__ void __launch_bounds__(128) chunk_kv() {
    __shared__ __half Ks[CH * LDAh];
    __shared__ __half Vs[CH * LDAh];
    const int ch = blockIdx.x, bh = blockIdx.y;
    const int b = bh >> 4, h = bh & 15;
    const int tid = threadIdx.x, w = tid >> 5;

    const __half* Kg = g_qkv + (size_t)(b * T_ + ch * CH) * NQKV + DM + h * DH;
    const __half* Vg = g_qkv + (size_t)(b * T_ + ch * CH) * NQKV + 2 * DM + h * DH;
#pragma unroll
    for (int i = 0; i < 4; i++) {              // 64x64 halves = 512 uint4 each
        int id = tid + i * 128;
        int r = id >> 3, c8 = (id & 7) * 8;
        *(uint4*)(Ks + r * LDAh + c8) = *(const uint4*)(Kg + (size_t)r * NQKV + c8);
        *(uint4*)(Vs + r * LDAh + c8) = *(const uint4*)(Vg + (size_t)r * NQKV + c8);
    }
    __syncthreads();

    wmma::fragment<wmma::accumulator, 16, 16, 16, float> acc[4];
#pragma unroll
    for (int i = 0; i < 4; i++) wmma::fill_fragment(acc[i], 0.0f);

#pragma unroll
    for (int kk = 0; kk < 4; kk++) {           // s-dimension in steps of 16
        wmma::fragment<wmma::matrix_a, 16, 16, 16, __half, wmma::col_major> a;
        wmma::load_matrix_sync(a, Ks + (kk * 16) * LDAh + w * 16, LDAh);
#pragma unroll
        for (int nf = 0; nf < 4; nf++) {
            HFragB bb;
            wmma::load_matrix_sync(bb, Vs + (kk * 16) * LDAh + nf * 16, LDAh);
            wmma::mma_sync(acc[nf], a, bb, acc[nf]);
        }
    }

    float* out = g_kv + ((size_t)bh * NCH + ch) * DH * DH;
#pragma unroll
    for (int nf = 0; nf < 4; nf++)
        wmma::store_matrix_sync(out + (w * 16) * DH + nf * 16, acc[nf], DH,
                                wmma::mem_row_major);
}

// ---------------------------------------------------------------------------
// Phase 2: exclusive prefix over chunks (fp32 exact).
// ---------------------------------------------------------------------------
__global__ void __launch_bounds__(512) prefix_kv() {
    const int bh = blockIdx.y;
    const int e  = blockIdx.x * 512 + threadIdx.x;
    const size_t base = (size_t)bh * NCH * DH * DH;
    float run = 0.0f;
#pragma unroll
    for (int c = 0; c < NCH; c++) {
        g_m[base + (size_t)c * (DH * DH) + e] = run;
        run += g_kv[base + (size_t)c * (DH * DH) + e];
    }
}

// ---------------------------------------------------------------------------
// Phase 3: O_c = Q_c @ M_c + mask(Q_c K_c^T) @ V_c, all fp16 MMA / fp32 acc.
// ---------------------------------------------------------------------------
#define ATTN_SMEM (5 * 64 * LDAh * 2 + 64 * 68 * 4)   // 63488 B

__global__ void __launch_bounds__(128) attn_chunk() {
    extern __shared__ __half smh[];
    __half* Qs = smh;                 // 64 x 72 halves each
    __half* Ks = Qs + 64 * LDAh;
    __half* Vs = Ks + 64 * LDAh;
    __half* Ms = Vs + 64 * LDAh;
    __half* Sh = Ms + 64 * LDAh;
    float*  Ss = (float*)(Sh + 64 * LDAh);   // 64 x 68 fp32

    const int ch = blockIdx.x, bh = blockIdx.y;
    const int b = bh >> 4, h = bh & 15;
    const int t0 = ch * CH;
    const int tid = threadIdx.x, w = tid >> 5, lane = tid & 31;

    const __half* Qg = g_qkv + (size_t)(b * T_ + t0) * NQKV + h * DH;
    const __half* Kg = Qg + DM;
    const __half* Vg = Qg + 2 * DM;
    const float*  Mg = g_m + ((size_t)bh * NCH + ch) * DH * DH;

#pragma unroll
    for (int i = 0; i < 4; i++) {             // Q,K,V: 512 uint4 each
        int id = tid + i * 128;
        int r = id >> 3, c8 = (id & 7) * 8;
        *(uint4*)(Qs + r * LDAh + c8) = *(const uint4*)(Qg + (size_t)r * NQKV + c8);
        *(uint4*)(Ks + r * LDAh + c8) = *(const uint4*)(Kg + (size_t)r * NQKV + c8);
        *(uint4*)(Vs + r * LDAh + c8) = *(const uint4*)(Vg + (size_t)r * NQKV + c8);
    }
#pragma unroll
    for (int i = 0; i < 8; i++) {             // M: 64x64 fp32 -> fp16 smem
        int id = tid + i * 128;
        int r = id >> 4, c4 = (id & 15) * 4;
        float4 mv = *(const float4*)(Mg + id * 4);
        __half hm[4] = {__float2half_rn(mv.x), __float2half_rn(mv.y),
                        __float2half_rn(mv.z), __float2half_rn(mv.w)};
        *(uint2*)(Ms + r * LDAh + c4) = *(uint2*)hm;
    }
    __syncthreads();

    wmma::fragment<wmma::accumulator, 16, 16, 16, float> o[4];
#pragma unroll
    for (int i = 0; i < 4; i++) wmma::fill_fragment(o[i], 0.0f);

    // (a) O = Q @ M
#pragma unroll
    for (int kk = 0; kk < 4; kk++) {
        HFragA a;
        wmma::load_matrix_sync(a, Qs + (w * 16) * LDAh + kk * 16, LDAh);
#pragma unroll
        for (int nf = 0; nf < 4; nf++) {
            HFragB bb;
            wmma::load_matrix_sync(bb, Ms + (kk * 16) * LDAh + nf * 16, LDAh);
            wmma::mma_sync(o[nf], a, bb, o[nf]);
        }
    }

    // (b) S = Q @ K^T
    wmma::fragment<wmma::accumulator, 16, 16, 16, float> s_acc[4];
#pragma unroll
    for (int i = 0; i < 4; i++) wmma::fill_fragment(s_acc[i], 0.0f);
#pragma unroll
    for (int kk = 0; kk < 4; kk++) {
        HFragA a;
        wmma::load_matrix_sync(a, Qs + (w * 16) * LDAh + kk * 16, LDAh);
#pragma unroll
        for (int nf = 0; nf < 4; nf++) {
            wmma::fragment<wmma::matrix_b, 16, 16, 16, __half, wmma::col_major> bb;
            wmma::load_matrix_sync(bb, Ks + (nf * 16) * LDAh + kk * 16, LDAh);
            wmma::mma_sync(s_acc[nf], a, bb, s_acc[nf]);
        }
    }
#pragma unroll
    for (int nf = 0; nf < 4; nf++)
        wmma::store_matrix_sync(Ss + (w * 16) * 68 + nf * 16, s_acc[nf], 68,
                                wmma::mem_row_major);
    __syncwarp();

    // strictly-lower mask (keep col < row) + fp16 convert
#pragma unroll
    for (int i = 0; i < 16; i++) {
#pragma unroll
        for (int c2 = 0; c2 < 2; c2++) {
            int c = c2 * 32 + lane;
            float v = (c < w * 16 + i) ? Ss[(w * 16 + i) * 68 + c] : 0.0f;
            Sh[(w * 16 + i) * LDAh + c] = __float2half_rn(v);
        }
    }
    __syncwarp();

    // (c) O += S @ V
#pragma unroll
    for (int kk = 0; kk < 4; kk++) {
        HFragA a;
        wmma::load_matrix_sync(a, Sh + (w * 16) * LDAh + kk * 16, LDAh);
#pragma unroll
        for (int nf = 0; nf < 4; nf++) {
            HFragB bb;
            wmma::load_matrix_sync(bb, Vs + (kk * 16) * LDAh + nf * 16, LDAh);
            wmma::mma_sync(o[nf], a, bb, o[nf]);
        }
    }

    // Epilogue: O -> fp16 global
#pragma unroll
    for (int nf = 0; nf < 4; nf++)
        wmma::store_matrix_sync(Ss + (w * 16) * 68 + nf * 16, o[nf], 68,
                                wmma::mem_row_major);
    __syncwarp();

    __half* Hg = g_ah + (size_t)(b * T_ + t0 + w * 16) * DM + h * DH;
#pragma unroll
    for (int i = 0; i < 16; i++) {
#pragma unroll
        for (int c2 = 0; c2 < 2; c2++) {
            int c = c2 * 32 + lane;
            Hg[(size_t)i * DM + c] = __float2half_rn(Ss[(w * 16 + i) * 68 + c]);
        }
    }
}

// ---------------------------------------------------------------------------
extern "C" void kernel_launch(void* const* d_in, const int* in_sizes, int n_in,
                              void* d_out, int out_size) {
    const float* x  = (const float*)d_in[0];
    const float* Wq = (const float*)d_in[1];
    const float* Wk = (const float*)d_in[2];
    const float* Wv = (const float*)d_in[3];
    const float* Wo = (const float*)d_in[4];

    __half *xh, *woh, *qkv, *ah;
    cudaGetSymbolAddress((void**)&xh,  g_xh);
    cudaGetSymbolAddress((void**)&woh, g_woh);
    cudaGetSymbolAddress((void**)&qkv, g_qkv);
    cudaGetSymbolAddress((void**)&ah,  g_ah);
    __half* wqkv;
    cudaGetSymbolAddress((void**)&wqkv, g_wqkv);

    cudaFuncSetAttribute(gemm_h<NQKV, true>, cudaFuncAttributeMaxDynamicSharedMemorySize, GEMM_SMEM);
    cudaFuncSetAttribute(gemm_h<DM, false>,  cudaFuncAttributeMaxDynamicSharedMemorySize, GEMM_SMEM);
    cudaFuncSetAttribute(attn_chunk,         cudaFuncAttributeMaxDynamicSharedMemorySize, ATTN_SMEM);

    // Prepass (3 launches): x, packed QKV weights, Wo
    tofp16<<<ROWS * DM / 8 / 256, 256>>>((const float4*)x, (uint4*)xh);
    pack_qkv<<<dim3(DM * DM / 8 / 256, 3), 256>>>((const float4*)Wq, (const float4*)Wk,
                                                  (const float4*)Wv);
    tofp16<<<DM * DM / 8 / 256, 256>>>((const float4*)Wo, (uint4*)woh);

    // Fused QKV GEMM: [4096,1024] @ [1024,3072]
    gemm_h<NQKV, true><<<dim3(NQKV / 128, ROWS / 128), 256, GEMM_SMEM>>>(xh, wqkv, qkv);

    chunk_kv<<<dim3(NCH, BH), 128>>>();
    prefix_kv<<<dim3(8, BH), 512>>>();
    attn_chunk<<<dim3(NCH, BH), 128, ATTN_SMEM>>>();

    // Output projection: [4096,1024] @ [1024,1024] -> fp32 d_out
    gemm_h<DM, false><<<dim3(DM / 128, ROWS / 128), 256, GEMM_SMEM>>>(ah, woh, (float*)d_out);
}